// round 2
// baseline (speedup 1.0000x reference)
#include <cuda_runtime.h>
#include <math.h>

#define NTOK   8192      // B*T
#define DM     1024
#define DFF    4096
#define TSEQ   2048
#define NH     16
#define DH     64

// ---------------- scratch (static device globals; no allocation) ----------------
__device__ float g_h  [NTOK * DM];       // LN output (reused for ln1 and ln2)
__device__ float g_qkv[NTOK * 3 * DM];   // qkv projections
__device__ float g_o  [NTOK * DM];       // attention output
__device__ float g_x2 [NTOK * DM];       // residual after attention
__device__ float g_ff [NTOK * DFF];      // gelu(h2 @ w1 + b1)

// ---------------- LayerNorm: one block per row of 1024 ----------------
__global__ void __launch_bounds__(256) ln_kernel(
    const float* __restrict__ x, const float* __restrict__ g,
    const float* __restrict__ b, float* __restrict__ out)
{
    const int row = blockIdx.x;
    const float* xr = x + (size_t)row * DM;
    float v[4];
    float s = 0.f, s2 = 0.f;
#pragma unroll
    for (int i = 0; i < 4; i++) {
        v[i] = xr[threadIdx.x + i * 256];
        s += v[i]; s2 += v[i] * v[i];
    }
#pragma unroll
    for (int off = 16; off; off >>= 1) {
        s  += __shfl_xor_sync(0xffffffffu, s,  off);
        s2 += __shfl_xor_sync(0xffffffffu, s2, off);
    }
    __shared__ float ss[8], ss2[8];
    const int w = threadIdx.x >> 5, ln = threadIdx.x & 31;
    if (ln == 0) { ss[w] = s; ss2[w] = s2; }
    __syncthreads();
    s = 0.f; s2 = 0.f;
#pragma unroll
    for (int i = 0; i < 8; i++) { s += ss[i]; s2 += ss2[i]; }
    const float mean = s * (1.0f / DM);
    const float var  = s2 * (1.0f / DM) - mean * mean;
    const float rstd = rsqrtf(var + 1e-5f);
    float* orow = out + (size_t)row * DM;
#pragma unroll
    for (int i = 0; i < 4; i++) {
        const int c = threadIdx.x + i * 256;
        orow[c] = (v[i] - mean) * rstd * g[c] + b[c];
    }
}

// ---------------- fp32 SGEMM: 128x128 tile, BK=8, 8x8 per thread ----------------
// EPI: 0 = none, 1 = bias + exact GELU, 2 = bias + residual
__device__ __forceinline__ float gelu_exact(float x) {
    return 0.5f * x * (1.0f + erff(x * 0.70710678118654752f));
}

template<int EPI>
__global__ void __launch_bounds__(256) gemm128(
    const float* __restrict__ A, const float* __restrict__ Bm,
    const float* __restrict__ bias, const float* __restrict__ res,
    float* __restrict__ C, int M, int N, int K)
{
    __shared__ float As[8][132];
    __shared__ float Bs[8][128];
    const int tid = threadIdx.x;
    const int tx = tid & 15, ty = tid >> 4;
    const int bm = blockIdx.y * 128, bn = blockIdx.x * 128;

    const int ar = tid >> 1;            // 0..127 (row within A tile)
    const int ac = (tid & 1) * 4;       // 0 or 4 (col group within BK)
    const int br = tid >> 5;            // 0..7
    const int bc = (tid & 31) * 4;      // 0..124

    float acc[8][8];
#pragma unroll
    for (int i = 0; i < 8; i++)
#pragma unroll
        for (int j = 0; j < 8; j++) acc[i][j] = 0.f;

    for (int k0 = 0; k0 < K; k0 += 8) {
        float4 av = *reinterpret_cast<const float4*>(&A [(size_t)(bm + ar) * K + k0 + ac]);
        float4 bv = *reinterpret_cast<const float4*>(&Bm[(size_t)(k0 + br) * N + bn + bc]);
        As[ac + 0][ar] = av.x; As[ac + 1][ar] = av.y;
        As[ac + 2][ar] = av.z; As[ac + 3][ar] = av.w;
        *reinterpret_cast<float4*>(&Bs[br][bc]) = bv;
        __syncthreads();
#pragma unroll
        for (int k = 0; k < 8; k++) {
            float a[8], b[8];
#pragma unroll
            for (int i = 0; i < 8; i++) a[i] = As[k][ty * 8 + i];
#pragma unroll
            for (int j = 0; j < 8; j++) b[j] = Bs[k][tx * 8 + j];
#pragma unroll
            for (int i = 0; i < 8; i++)
#pragma unroll
                for (int j = 0; j < 8; j++)
                    acc[i][j] = fmaf(a[i], b[j], acc[i][j]);
        }
        __syncthreads();
    }

#pragma unroll
    for (int i = 0; i < 8; i++) {
        const int row = bm + ty * 8 + i;
#pragma unroll
        for (int j = 0; j < 8; j++) {
            const int col = bn + tx * 8 + j;
            float v = acc[i][j];
            if (EPI == 1) { v += bias[col]; v = gelu_exact(v); }
            if (EPI == 2) { v += bias[col] + res[(size_t)row * N + col]; }
            C[(size_t)row * N + col] = v;
        }
    }
}

// ---------------- causal flash attention, fp32 ----------------
// grid: (32 q-tiles, 64 b*h). 256 threads. dh = 64.
// smem: Qs[64][68] (pre-scaled), Ks transposed [d][68], Vs natural [k][68], Ss[64][68].
#define ALD 68
#define ATT_SMEM (4 * 64 * ALD * 4)

__global__ void __launch_bounds__(256) attn_kernel(
    const float* __restrict__ qkv, float* __restrict__ O)
{
    const int qt = blockIdx.x;          // 0..31
    const int bh = blockIdx.y;          // 0..63
    const int bb = bh >> 4, hh = bh & 15;
    const int tid = threadIdx.x;
    const int tx = tid & 15, ty = tid >> 4;
    const size_t rowbase = (size_t)bb * TSEQ;
    const int qoff = hh * DH;
    const int koff = DM + hh * DH;
    const int voff = 2 * DM + hh * DH;
    const int q0 = qt * 64;

    extern __shared__ float sm[];
    float* Qs = sm;                     // [r][d]
    float* Ks = sm + 64 * ALD;          // [d][r]  (transposed)
    float* Vs = sm + 2 * 64 * ALD;      // [r][d]
    float* Ss = sm + 3 * 64 * ALD;      // [r][c]

    // load + pre-scale Q
    for (int e = tid; e < 4096; e += 256) {
        const int r = e >> 6, d = e & 63;
        Qs[r * ALD + d] = qkv[(rowbase + q0 + r) * (size_t)(3 * DM) + qoff + d] * 0.125f;
    }

    float acc[4][4];
    float m[4], lsum[4];
#pragma unroll
    for (int i = 0; i < 4; i++) {
        m[i] = -1e30f; lsum[i] = 0.f;
#pragma unroll
        for (int j = 0; j < 4; j++) acc[i][j] = 0.f;
    }

    for (int kt = 0; kt <= qt; kt++) {
        const int k0 = kt * 64;
        __syncthreads();   // prior tile's reads of Ks/Vs/Ss done; Q load (1st iter)
        for (int e = tid; e < 4096; e += 256) {
            const int r = e >> 6, d = e & 63;
            const size_t base = (rowbase + k0 + r) * (size_t)(3 * DM);
            Ks[d * ALD + r] = qkv[base + koff + d];   // transposed
            Vs[r * ALD + d] = qkv[base + voff + d];
        }
        __syncthreads();

        // S = Q K^T (scaled)
        float s[4][4];
#pragma unroll
        for (int i = 0; i < 4; i++)
#pragma unroll
            for (int j = 0; j < 4; j++) s[i][j] = 0.f;
        for (int d = 0; d < 64; d++) {
            float a[4], b[4];
#pragma unroll
            for (int i = 0; i < 4; i++) a[i] = Qs[(ty * 4 + i) * ALD + d];
#pragma unroll
            for (int j = 0; j < 4; j++) b[j] = Ks[d * ALD + tx * 4 + j];
#pragma unroll
            for (int i = 0; i < 4; i++)
#pragma unroll
                for (int j = 0; j < 4; j++)
                    s[i][j] = fmaf(a[i], b[j], s[i][j]);
        }
        // causal mask (only on diagonal tile; k0 == q0 there)
        if (kt == qt) {
#pragma unroll
            for (int i = 0; i < 4; i++)
#pragma unroll
                for (int j = 0; j < 4; j++)
                    if (tx * 4 + j > ty * 4 + i) s[i][j] = -1e30f;
        }

        // online softmax update
#pragma unroll
        for (int i = 0; i < 4; i++) {
            float mx = fmaxf(fmaxf(s[i][0], s[i][1]), fmaxf(s[i][2], s[i][3]));
#pragma unroll
            for (int off = 8; off; off >>= 1)
                mx = fmaxf(mx, __shfl_xor_sync(0xffffffffu, mx, off, 16));
            const float mn = fmaxf(m[i], mx);
            const float alpha = __expf(m[i] - mn);
            float rs = 0.f;
#pragma unroll
            for (int j = 0; j < 4; j++) {
                s[i][j] = __expf(s[i][j] - mn);
                rs += s[i][j];
            }
#pragma unroll
            for (int off = 8; off; off >>= 1)
                rs += __shfl_xor_sync(0xffffffffu, rs, off, 16);
            lsum[i] = lsum[i] * alpha + rs;
            m[i] = mn;
#pragma unroll
            for (int j = 0; j < 4; j++) {
                acc[i][j] *= alpha;
                Ss[(ty * 4 + i) * ALD + tx * 4 + j] = s[i][j];
            }
        }
        __syncthreads();

        // O += P V
        for (int kk = 0; kk < 64; kk++) {
            float a[4], b[4];
#pragma unroll
            for (int i = 0; i < 4; i++) a[i] = Ss[(ty * 4 + i) * ALD + kk];
#pragma unroll
            for (int j = 0; j < 4; j++) b[j] = Vs[kk * ALD + tx * 4 + j];
#pragma unroll
            for (int i = 0; i < 4; i++)
#pragma unroll
                for (int j = 0; j < 4; j++)
                    acc[i][j] = fmaf(a[i], b[j], acc[i][j]);
        }
    }

    // write O (layout [token][h*64 + d])
#pragma unroll
    for (int i = 0; i < 4; i++) {
        const float inv = 1.0f / lsum[i];
        const size_t orow = (rowbase + q0 + ty * 4 + i) * (size_t)DM + hh * DH;
#pragma unroll
        for (int j = 0; j < 4; j++)
            O[orow + tx * 4 + j] = acc[i][j] * inv;
    }
}

// ---------------- launcher ----------------
extern "C" void kernel_launch(void* const* d_in, const int* in_sizes, int n_in,
                              void* d_out, int out_size)
{
    const float* x     = (const float*)d_in[0];
    const float* ln1_g = (const float*)d_in[1];
    const float* ln1_b = (const float*)d_in[2];
    const float* w_qkv = (const float*)d_in[3];
    const float* w_out = (const float*)d_in[4];
    const float* b_out = (const float*)d_in[5];
    const float* ln2_g = (const float*)d_in[6];
    const float* ln2_b = (const float*)d_in[7];
    const float* w1    = (const float*)d_in[8];
    const float* b1    = (const float*)d_in[9];
    const float* w2    = (const float*)d_in[10];
    const float* b2    = (const float*)d_in[11];
    float* out = (float*)d_out;

    float *h, *qkv, *o, *x2, *ff;
    cudaGetSymbolAddress((void**)&h,   g_h);
    cudaGetSymbolAddress((void**)&qkv, g_qkv);
    cudaGetSymbolAddress((void**)&o,   g_o);
    cudaGetSymbolAddress((void**)&x2,  g_x2);
    cudaGetSymbolAddress((void**)&ff,  g_ff);

    cudaFuncSetAttribute(attn_kernel,
                         cudaFuncAttributeMaxDynamicSharedMemorySize, ATT_SMEM);

    // 1) h = LN1(x)
    ln_kernel<<<NTOK, 256>>>(x, ln1_g, ln1_b, h);
    // 2) qkv = h @ w_qkv
    gemm128<0><<<dim3(3 * DM / 128, NTOK / 128), 256>>>(h, w_qkv, nullptr, nullptr,
                                                        qkv, NTOK, 3 * DM, DM);
    // 3) o = causal_attention(qkv)
    attn_kernel<<<dim3(TSEQ / 64, 4 * NH), 256, ATT_SMEM>>>(qkv, o);
    // 4) x2 = x + o @ w_out + b_out
    gemm128<2><<<dim3(DM / 128, NTOK / 128), 256>>>(o, w_out, b_out, x,
                                                    x2, NTOK, DM, DM);
    // 5) h = LN2(x2)
    ln_kernel<<<NTOK, 256>>>(x2, ln2_g, ln2_b, h);
    // 6) ff = gelu(h @ w1 + b1)
    gemm128<1><<<dim3(DFF / 128, NTOK / 128), 256>>>(h, w1, b1, nullptr,
                                                     ff, NTOK, DFF, DM);
    // 7) out = x2 + ff @ w2 + b2   (FIX: K = DFF, was DM)
    gemm128<2><<<dim3(DM / 128, NTOK / 128), 256>>>(ff, w2, b2, x2,
                                                    out, NTOK, DM, DFF);
}

// round 3
// speedup vs baseline: 2.2696x; 2.2696x over previous
#include <cuda_runtime.h>
#include <math.h>
#include <stdint.h>

#define NTOK   8192      // B*T
#define DM     1024
#define DFF    4096
#define TSEQ   2048
#define NH     16
#define DH     64

// ---------------- scratch (static device globals; no allocation) ----------------
__device__ float g_h  [NTOK * DM];       // LN output (reused for ln1 and ln2)
__device__ float g_qkv[NTOK * 3 * DM];   // qkv projections
__device__ float g_o  [NTOK * DM];       // attention output
__device__ float g_x2 [NTOK * DM];       // residual after attention
__device__ float g_ff [NTOK * DFF];      // gelu(h2 @ w1 + b1)

// ---------------- LayerNorm: one block per row of 1024 ----------------
__global__ void __launch_bounds__(256) ln_kernel(
    const float* __restrict__ x, const float* __restrict__ g,
    const float* __restrict__ b, float* __restrict__ out)
{
    const int row = blockIdx.x;
    const float* xr = x + (size_t)row * DM;
    float v[4];
    float s = 0.f, s2 = 0.f;
#pragma unroll
    for (int i = 0; i < 4; i++) {
        v[i] = xr[threadIdx.x + i * 256];
        s += v[i]; s2 += v[i] * v[i];
    }
#pragma unroll
    for (int off = 16; off; off >>= 1) {
        s  += __shfl_xor_sync(0xffffffffu, s,  off);
        s2 += __shfl_xor_sync(0xffffffffu, s2, off);
    }
    __shared__ float ss[8], ss2[8];
    const int w = threadIdx.x >> 5, ln = threadIdx.x & 31;
    if (ln == 0) { ss[w] = s; ss2[w] = s2; }
    __syncthreads();
    s = 0.f; s2 = 0.f;
#pragma unroll
    for (int i = 0; i < 8; i++) { s += ss[i]; s2 += ss2[i]; }
    const float mean = s * (1.0f / DM);
    const float var  = s2 * (1.0f / DM) - mean * mean;
    const float rstd = rsqrtf(var + 1e-5f);
    float* orow = out + (size_t)row * DM;
#pragma unroll
    for (int i = 0; i < 4; i++) {
        const int c = threadIdx.x + i * 256;
        orow[c] = (v[i] - mean) * rstd * g[c] + b[c];
    }
}

// ---------------- TF32 tensor-core GEMM ----------------
// C[M,N] = A[M,K] @ B[K,N] (+ epilogue). 128x128 tile, BK=32, 8 warps,
// double-buffered cp.async. A frags via ldmatrix.x4, B frags via scalar LDS.
// EPI: 0 none, 1 bias+exact GELU, 2 bias+residual.

__device__ __forceinline__ float gelu_exact(float x) {
    return 0.5f * x * (1.0f + erff(x * 0.70710678118654752f));
}

__device__ __forceinline__ uint32_t f2tf(float f) {
    uint32_t u;
    asm("cvt.rna.tf32.f32 %0, %1;" : "=r"(u) : "f"(f));
    return u;
}

__device__ __forceinline__ void ldsm4(uint32_t& r0, uint32_t& r1,
                                      uint32_t& r2, uint32_t& r3, uint32_t addr) {
    asm volatile("ldmatrix.sync.aligned.m8n8.x4.shared.b16 {%0,%1,%2,%3}, [%4];\n"
                 : "=r"(r0), "=r"(r1), "=r"(r2), "=r"(r3) : "r"(addr));
}

__device__ __forceinline__ void mma_tf32(float* c,
    uint32_t a0, uint32_t a1, uint32_t a2, uint32_t a3, uint32_t b0, uint32_t b1) {
    asm volatile(
        "mma.sync.aligned.m16n8k8.row.col.f32.tf32.tf32.f32 "
        "{%0,%1,%2,%3}, {%4,%5,%6,%7}, {%8,%9}, {%0,%1,%2,%3};\n"
        : "+f"(c[0]), "+f"(c[1]), "+f"(c[2]), "+f"(c[3])
        : "r"(a0), "r"(a1), "r"(a2), "r"(a3), "r"(b0), "r"(b1));
}

__device__ __forceinline__ void cp16(float* dst, const float* src) {
    uint32_t d = (uint32_t)__cvta_generic_to_shared(dst);
    asm volatile("cp.async.cg.shared.global [%0], [%1], 16;\n" :: "r"(d), "l"(src));
}

#define ASTRIDE 36               // floats per A smem row (128B data + 16B pad)
#define BSTRIDE 136              // floats per B smem row (512B data + 32B pad)
#define AS_SZ   (128 * ASTRIDE)  // 4608 floats
#define BS_SZ   (32 * BSTRIDE)   // 4352 floats
#define STAGE_F (AS_SZ + BS_SZ)  // floats per stage
#define GEMM_SMEM (2 * STAGE_F * 4)

template<int EPI>
__global__ void __launch_bounds__(256) gemm_tf32(
    const float* __restrict__ A, const float* __restrict__ Bm,
    const float* __restrict__ bias, const float* __restrict__ res,
    float* __restrict__ C, int M, int N, int K)
{
    extern __shared__ float sm[];
    const int tid  = threadIdx.x;
    const int lane = tid & 31, wid = tid >> 5;
    const int bm = blockIdx.y * 128, bn = blockIdx.x * 128;
    const int wm = (wid >> 2) * 64;       // warp m-base within tile (0/64)
    const int wn = (wid & 3) * 32;        // warp n-base within tile (0..96)
    const int gr = lane >> 2, tg = lane & 3;

    const uint32_t smem_u32 = (uint32_t)__cvta_generic_to_shared(sm);
    // per-lane ldmatrix row/col offsets (within warp A tile)
    const int arow = wm + (lane & 7) + 8 * ((lane >> 3) & 1);
    const int acol = (lane >> 4) * 4;

    float acc[4][4][4];
#pragma unroll
    for (int i = 0; i < 4; i++)
#pragma unroll
        for (int j = 0; j < 4; j++)
#pragma unroll
            for (int r = 0; r < 4; r++) acc[i][j][r] = 0.f;

    const int KT = K >> 5;   // K / 32

    // ---- stage issue: A rows [bm,bm+128) x k[k0,k0+32); B rows k x n[bn,bn+128)
    auto issue = [&](int kt, int stg) {
        const int k0 = kt << 5;
        float* As = sm + stg * STAGE_F;
        float* Bs = As + AS_SZ;
#pragma unroll
        for (int i = 0; i < 4; i++) {
            const int c = tid + i * 256;
            const int row = c >> 3, kc = (c & 7) * 4;
            cp16(As + row * ASTRIDE + kc, A + (size_t)(bm + row) * K + k0 + kc);
        }
#pragma unroll
        for (int i = 0; i < 4; i++) {
            const int c = tid + i * 256;
            const int row = c >> 5, nc = (c & 31) * 4;
            cp16(Bs + row * BSTRIDE + nc, Bm + (size_t)(k0 + row) * N + bn + nc);
        }
    };

    issue(0, 0);
    asm volatile("cp.async.commit_group;\n");

    for (int kt = 0; kt < KT; kt++) {
        const int cur = kt & 1;
        if (kt + 1 < KT) {
            issue(kt + 1, cur ^ 1);
            asm volatile("cp.async.commit_group;\n");
            asm volatile("cp.async.wait_group 1;\n");
        } else {
            asm volatile("cp.async.wait_group 0;\n");
        }
        __syncthreads();

        const uint32_t As_u = smem_u32 + (cur * STAGE_F) * 4;
        const float* Bs = sm + cur * STAGE_F + AS_SZ;

#pragma unroll
        for (int ks = 0; ks < 4; ks++) {
            // B fragments: conflict-free (bank = 8k + n)
            uint32_t rb[4][2];
#pragma unroll
            for (int ni = 0; ni < 4; ni++) {
                const int nidx = wn + ni * 8 + gr;
                rb[ni][0] = f2tf(Bs[(ks * 8 + tg)     * BSTRIDE + nidx]);
                rb[ni][1] = f2tf(Bs[(ks * 8 + tg + 4) * BSTRIDE + nidx]);
            }
            // A fragments via ldmatrix
            uint32_t ra[4][4];
#pragma unroll
            for (int mi = 0; mi < 4; mi++) {
                const uint32_t addr = As_u +
                    (((arow + mi * 16) * ASTRIDE) + acol + ks * 8) * 4;
                ldsm4(ra[mi][0], ra[mi][1], ra[mi][2], ra[mi][3], addr);
#pragma unroll
                for (int r = 0; r < 4; r++)
                    ra[mi][r] = f2tf(__uint_as_float(ra[mi][r]));
            }
#pragma unroll
            for (int mi = 0; mi < 4; mi++)
#pragma unroll
                for (int ni = 0; ni < 4; ni++)
                    mma_tf32(acc[mi][ni], ra[mi][0], ra[mi][1], ra[mi][2], ra[mi][3],
                             rb[ni][0], rb[ni][1]);
        }
        __syncthreads();
    }

    // ---- epilogue ----
#pragma unroll
    for (int mi = 0; mi < 4; mi++) {
        const int row0 = bm + wm + mi * 16 + gr;
        const int row1 = row0 + 8;
#pragma unroll
        for (int ni = 0; ni < 4; ni++) {
            const int col = bn + wn + ni * 8 + 2 * tg;
            float v0 = acc[mi][ni][0], v1 = acc[mi][ni][1];
            float v2 = acc[mi][ni][2], v3 = acc[mi][ni][3];
            if (EPI == 1) {
                const float bb0 = bias[col], bb1 = bias[col + 1];
                v0 = gelu_exact(v0 + bb0); v1 = gelu_exact(v1 + bb1);
                v2 = gelu_exact(v2 + bb0); v3 = gelu_exact(v3 + bb1);
            }
            if (EPI == 2) {
                const float bb0 = bias[col], bb1 = bias[col + 1];
                const float2 r0 = *reinterpret_cast<const float2*>(&res[(size_t)row0 * N + col]);
                const float2 r1 = *reinterpret_cast<const float2*>(&res[(size_t)row1 * N + col]);
                v0 += bb0 + r0.x; v1 += bb1 + r0.y;
                v2 += bb0 + r1.x; v3 += bb1 + r1.y;
            }
            *reinterpret_cast<float2*>(&C[(size_t)row0 * N + col]) = make_float2(v0, v1);
            *reinterpret_cast<float2*>(&C[(size_t)row1 * N + col]) = make_float2(v2, v3);
        }
    }
}

// ---------------- causal flash attention, fp32 ----------------
#define ALD 68
#define ATT_SMEM (4 * 64 * ALD * 4)

__global__ void __launch_bounds__(256) attn_kernel(
    const float* __restrict__ qkv, float* __restrict__ O)
{
    const int qt = blockIdx.x;          // 0..31
    const int bh = blockIdx.y;          // 0..63
    const int bb = bh >> 4, hh = bh & 15;
    const int tid = threadIdx.x;
    const int tx = tid & 15, ty = tid >> 4;
    const size_t rowbase = (size_t)bb * TSEQ;
    const int qoff = hh * DH;
    const int koff = DM + hh * DH;
    const int voff = 2 * DM + hh * DH;
    const int q0 = qt * 64;

    extern __shared__ float sm[];
    float* Qs = sm;                     // [r][d]
    float* Ks = sm + 64 * ALD;          // [d][r]  (transposed)
    float* Vs = sm + 2 * 64 * ALD;      // [r][d]
    float* Ss = sm + 3 * 64 * ALD;      // [r][c]

    for (int e = tid; e < 4096; e += 256) {
        const int r = e >> 6, d = e & 63;
        Qs[r * ALD + d] = qkv[(rowbase + q0 + r) * (size_t)(3 * DM) + qoff + d] * 0.125f;
    }

    float acc[4][4];
    float m[4], lsum[4];
#pragma unroll
    for (int i = 0; i < 4; i++) {
        m[i] = -1e30f; lsum[i] = 0.f;
#pragma unroll
        for (int j = 0; j < 4; j++) acc[i][j] = 0.f;
    }

    for (int kt = 0; kt <= qt; kt++) {
        const int k0 = kt * 64;
        __syncthreads();
        for (int e = tid; e < 4096; e += 256) {
            const int r = e >> 6, d = e & 63;
            const size_t base = (rowbase + k0 + r) * (size_t)(3 * DM);
            Ks[d * ALD + r] = qkv[base + koff + d];
            Vs[r * ALD + d] = qkv[base + voff + d];
        }
        __syncthreads();

        float s[4][4];
#pragma unroll
        for (int i = 0; i < 4; i++)
#pragma unroll
            for (int j = 0; j < 4; j++) s[i][j] = 0.f;
        for (int d = 0; d < 64; d++) {
            float a[4], b[4];
#pragma unroll
            for (int i = 0; i < 4; i++) a[i] = Qs[(ty * 4 + i) * ALD + d];
#pragma unroll
            for (int j = 0; j < 4; j++) b[j] = Ks[d * ALD + tx * 4 + j];
#pragma unroll
            for (int i = 0; i < 4; i++)
#pragma unroll
                for (int j = 0; j < 4; j++)
                    s[i][j] = fmaf(a[i], b[j], s[i][j]);
        }
        if (kt == qt) {
#pragma unroll
            for (int i = 0; i < 4; i++)
#pragma unroll
                for (int j = 0; j < 4; j++)
                    if (tx * 4 + j > ty * 4 + i) s[i][j] = -1e30f;
        }

#pragma unroll
        for (int i = 0; i < 4; i++) {
            float mx = fmaxf(fmaxf(s[i][0], s[i][1]), fmaxf(s[i][2], s[i][3]));
#pragma unroll
            for (int off = 8; off; off >>= 1)
                mx = fmaxf(mx, __shfl_xor_sync(0xffffffffu, mx, off, 16));
            const float mn = fmaxf(m[i], mx);
            const float alpha = __expf(m[i] - mn);
            float rs = 0.f;
#pragma unroll
            for (int j = 0; j < 4; j++) {
                s[i][j] = __expf(s[i][j] - mn);
                rs += s[i][j];
            }
#pragma unroll
            for (int off = 8; off; off >>= 1)
                rs += __shfl_xor_sync(0xffffffffu, rs, off, 16);
            lsum[i] = lsum[i] * alpha + rs;
            m[i] = mn;
#pragma unroll
            for (int j = 0; j < 4; j++) {
                acc[i][j] *= alpha;
                Ss[(ty * 4 + i) * ALD + tx * 4 + j] = s[i][j];
            }
        }
        __syncthreads();

        for (int kk = 0; kk < 64; kk++) {
            float a[4], b[4];
#pragma unroll
            for (int i = 0; i < 4; i++) a[i] = Ss[(ty * 4 + i) * ALD + kk];
#pragma unroll
            for (int j = 0; j < 4; j++) b[j] = Vs[kk * ALD + tx * 4 + j];
#pragma unroll
            for (int i = 0; i < 4; i++)
#pragma unroll
                for (int j = 0; j < 4; j++)
                    acc[i][j] = fmaf(a[i], b[j], acc[i][j]);
        }
    }

#pragma unroll
    for (int i = 0; i < 4; i++) {
        const float inv = 1.0f / lsum[i];
        const size_t orow = (rowbase + q0 + ty * 4 + i) * (size_t)DM + hh * DH;
#pragma unroll
        for (int j = 0; j < 4; j++)
            O[orow + tx * 4 + j] = acc[i][j] * inv;
    }
}

// ---------------- launcher ----------------
extern "C" void kernel_launch(void* const* d_in, const int* in_sizes, int n_in,
                              void* d_out, int out_size)
{
    const float* x     = (const float*)d_in[0];
    const float* ln1_g = (const float*)d_in[1];
    const float* ln1_b = (const float*)d_in[2];
    const float* w_qkv = (const float*)d_in[3];
    const float* w_out = (const float*)d_in[4];
    const float* b_out = (const float*)d_in[5];
    const float* ln2_g = (const float*)d_in[6];
    const float* ln2_b = (const float*)d_in[7];
    const float* w1    = (const float*)d_in[8];
    const float* b1    = (const float*)d_in[9];
    const float* w2    = (const float*)d_in[10];
    const float* b2    = (const float*)d_in[11];
    float* out = (float*)d_out;

    float *h, *qkv, *o, *x2, *ff;
    cudaGetSymbolAddress((void**)&h,   g_h);
    cudaGetSymbolAddress((void**)&qkv, g_qkv);
    cudaGetSymbolAddress((void**)&o,   g_o);
    cudaGetSymbolAddress((void**)&x2,  g_x2);
    cudaGetSymbolAddress((void**)&ff,  g_ff);

    cudaFuncSetAttribute(attn_kernel,
                         cudaFuncAttributeMaxDynamicSharedMemorySize, ATT_SMEM);
    cudaFuncSetAttribute(gemm_tf32<0>,
                         cudaFuncAttributeMaxDynamicSharedMemorySize, GEMM_SMEM);
    cudaFuncSetAttribute(gemm_tf32<1>,
                         cudaFuncAttributeMaxDynamicSharedMemorySize, GEMM_SMEM);
    cudaFuncSetAttribute(gemm_tf32<2>,
                         cudaFuncAttributeMaxDynamicSharedMemorySize, GEMM_SMEM);

    // 1) h = LN1(x)
    ln_kernel<<<NTOK, 256>>>(x, ln1_g, ln1_b, h);
    // 2) qkv = h @ w_qkv
    gemm_tf32<0><<<dim3(3 * DM / 128, NTOK / 128), 256, GEMM_SMEM>>>(
        h, w_qkv, nullptr, nullptr, qkv, NTOK, 3 * DM, DM);
    // 3) o = causal_attention(qkv)
    attn_kernel<<<dim3(TSEQ / 64, 4 * NH), 256, ATT_SMEM>>>(qkv, o);
    // 4) x2 = x + o @ w_out + b_out
    gemm_tf32<2><<<dim3(DM / 128, NTOK / 128), 256, GEMM_SMEM>>>(
        o, w_out, b_out, x, x2, NTOK, DM, DM);
    // 5) h = LN2(x2)
    ln_kernel<<<NTOK, 256>>>(x2, ln2_g, ln2_b, h);
    // 6) ff = gelu(h @ w1 + b1)
    gemm_tf32<1><<<dim3(DFF / 128, NTOK / 128), 256, GEMM_SMEM>>>(
        h, w1, b1, nullptr, ff, NTOK, DFF, DM);
    // 7) out = x2 + ff @ w2 + b2
    gemm_tf32<2><<<dim3(DM / 128, NTOK / 128), 256, GEMM_SMEM>>>(
        ff, w2, b2, x2, out, NTOK, DM, DFF);
}

// round 4
// speedup vs baseline: 3.3803x; 1.4894x over previous
#include <cuda_runtime.h>
#include <math.h>
#include <stdint.h>

#define NTOK   8192      // B*T
#define DM     1024
#define DFF    4096
#define TSEQ   2048
#define NH     16
#define DH     64

// ---------------- scratch (static device globals; no allocation) ----------------
__device__ float g_h  [NTOK * DM];       // LN output (tf32-rounded)
__device__ float g_qkv[NTOK * 3 * DM];   // qkv projections (tf32-rounded)
__device__ float g_o  [NTOK * DM];       // attention output (tf32-rounded)
__device__ float g_x2 [NTOK * DM];       // residual after attention (full fp32)
__device__ float g_ff [NTOK * DFF];      // gelu output (tf32-rounded)
__device__ float g_wc [DM*3*DM + DM*DM + DM*DFF + DFF*DM];  // tf32 weights

__device__ __forceinline__ uint32_t f2tf(float f) {
    uint32_t u;
    asm("cvt.rna.tf32.f32 %0, %1;" : "=r"(u) : "f"(f));
    return u;
}
__device__ __forceinline__ float f2tf_f(float f) {
    return __uint_as_float(f2tf(f));
}

// ---------------- weight pre-round to tf32 ----------------
__global__ void __launch_bounds__(256) round_kernel(
    const float* __restrict__ src, float* __restrict__ dst, int n)
{
    int i = (blockIdx.x * 256 + threadIdx.x) * 4;
    if (i < n) {
        float4 v = *reinterpret_cast<const float4*>(src + i);
        v.x = f2tf_f(v.x); v.y = f2tf_f(v.y);
        v.z = f2tf_f(v.z); v.w = f2tf_f(v.w);
        *reinterpret_cast<float4*>(dst + i) = v;
    }
}

// ---------------- LayerNorm (tf32-rounded output) ----------------
__global__ void __launch_bounds__(256) ln_kernel(
    const float* __restrict__ x, const float* __restrict__ g,
    const float* __restrict__ b, float* __restrict__ out)
{
    const int row = blockIdx.x;
    const float* xr = x + (size_t)row * DM;
    float v[4];
    float s = 0.f, s2 = 0.f;
#pragma unroll
    for (int i = 0; i < 4; i++) {
        v[i] = xr[threadIdx.x + i * 256];
        s += v[i]; s2 += v[i] * v[i];
    }
#pragma unroll
    for (int off = 16; off; off >>= 1) {
        s  += __shfl_xor_sync(0xffffffffu, s,  off);
        s2 += __shfl_xor_sync(0xffffffffu, s2, off);
    }
    __shared__ float ss[8], ss2[8];
    const int w = threadIdx.x >> 5, ln = threadIdx.x & 31;
    if (ln == 0) { ss[w] = s; ss2[w] = s2; }
    __syncthreads();
    s = 0.f; s2 = 0.f;
#pragma unroll
    for (int i = 0; i < 8; i++) { s += ss[i]; s2 += ss2[i]; }
    const float mean = s * (1.0f / DM);
    const float var  = s2 * (1.0f / DM) - mean * mean;
    const float rstd = rsqrtf(var + 1e-5f);
    float* orow = out + (size_t)row * DM;
#pragma unroll
    for (int i = 0; i < 4; i++) {
        const int c = threadIdx.x + i * 256;
        orow[c] = f2tf_f((v[i] - mean) * rstd * g[c] + b[c]);
    }
}

// ---------------- TF32 tensor-core GEMM (inputs pre-rounded) ----------------
// EPI: 0 none, 1 bias+GELU (tf32-rounded out), 2 bias+residual (fp32 out),
//      3 tf32-round only.
__device__ __forceinline__ float gelu_exact(float x) {
    return 0.5f * x * (1.0f + erff(x * 0.70710678118654752f));
}
__device__ __forceinline__ void ldsm4(uint32_t& r0, uint32_t& r1,
                                      uint32_t& r2, uint32_t& r3, uint32_t addr) {
    asm volatile("ldmatrix.sync.aligned.m8n8.x4.shared.b16 {%0,%1,%2,%3}, [%4];\n"
                 : "=r"(r0), "=r"(r1), "=r"(r2), "=r"(r3) : "r"(addr));
}
__device__ __forceinline__ void mma_tf32(float* c,
    uint32_t a0, uint32_t a1, uint32_t a2, uint32_t a3, uint32_t b0, uint32_t b1) {
    asm volatile(
        "mma.sync.aligned.m16n8k8.row.col.f32.tf32.tf32.f32 "
        "{%0,%1,%2,%3}, {%4,%5,%6,%7}, {%8,%9}, {%0,%1,%2,%3};\n"
        : "+f"(c[0]), "+f"(c[1]), "+f"(c[2]), "+f"(c[3])
        : "r"(a0), "r"(a1), "r"(a2), "r"(a3), "r"(b0), "r"(b1));
}
__device__ __forceinline__ void cp16(float* dst, const float* src) {
    uint32_t d = (uint32_t)__cvta_generic_to_shared(dst);
    asm volatile("cp.async.cg.shared.global [%0], [%1], 16;\n" :: "r"(d), "l"(src));
}

#define ASTRIDE 36
#define BSTRIDE 136
#define AS_SZ   (128 * ASTRIDE)
#define BS_SZ   (32 * BSTRIDE)
#define STAGE_F (AS_SZ + BS_SZ)
#define GEMM_SMEM (3 * STAGE_F * 4)

template<int EPI>
__global__ void __launch_bounds__(256) gemm_tf32(
    const float* __restrict__ A, const float* __restrict__ Bm,
    const float* __restrict__ bias, const float* __restrict__ res,
    float* __restrict__ C, int M, int N, int K)
{
    extern __shared__ float sm[];
    const int tid  = threadIdx.x;
    const int lane = tid & 31, wid = tid >> 5;
    const int bm = blockIdx.y * 128, bn = blockIdx.x * 128;
    const int wm = (wid >> 2) * 64;
    const int wn = (wid & 3) * 32;
    const int gr = lane >> 2, tg = lane & 3;

    const uint32_t smem_u32 = (uint32_t)__cvta_generic_to_shared(sm);
    const int arow = wm + (lane & 7) + 8 * ((lane >> 3) & 1);
    const int acol = (lane >> 4) * 4;

    float acc[4][4][4];
#pragma unroll
    for (int i = 0; i < 4; i++)
#pragma unroll
        for (int j = 0; j < 4; j++)
#pragma unroll
            for (int r = 0; r < 4; r++) acc[i][j][r] = 0.f;

    const int KT = K >> 5;

    auto issue = [&](int kt) {
        const int stg = kt % 3;
        const int k0 = kt << 5;
        float* As = sm + stg * STAGE_F;
        float* Bs = As + AS_SZ;
#pragma unroll
        for (int i = 0; i < 4; i++) {
            const int c = tid + i * 256;
            const int row = c >> 3, kc = (c & 7) * 4;
            cp16(As + row * ASTRIDE + kc, A + (size_t)(bm + row) * K + k0 + kc);
        }
#pragma unroll
        for (int i = 0; i < 4; i++) {
            const int c = tid + i * 256;
            const int row = c >> 5, nc = (c & 31) * 4;
            cp16(Bs + row * BSTRIDE + nc, Bm + (size_t)(k0 + row) * N + bn + nc);
        }
    };

    issue(0);
    asm volatile("cp.async.commit_group;\n");
    if (KT > 1) { issue(1); asm volatile("cp.async.commit_group;\n"); }

    for (int kt = 0; kt < KT; kt++) {
        const int cur = kt % 3;
        if (kt + 1 < KT) asm volatile("cp.async.wait_group 1;\n");
        else             asm volatile("cp.async.wait_group 0;\n");
        __syncthreads();
        if (kt + 2 < KT) { issue(kt + 2); asm volatile("cp.async.commit_group;\n"); }

        const uint32_t As_u = smem_u32 + (cur * STAGE_F) * 4;
        const float* Bs = sm + cur * STAGE_F + AS_SZ;

#pragma unroll
        for (int ks = 0; ks < 4; ks++) {
            uint32_t rb[4][2];
#pragma unroll
            for (int ni = 0; ni < 4; ni++) {
                const int nidx = wn + ni * 8 + gr;
                rb[ni][0] = __float_as_uint(Bs[(ks * 8 + tg)     * BSTRIDE + nidx]);
                rb[ni][1] = __float_as_uint(Bs[(ks * 8 + tg + 4) * BSTRIDE + nidx]);
            }
            uint32_t ra[4][4];
#pragma unroll
            for (int mi = 0; mi < 4; mi++) {
                const uint32_t addr = As_u +
                    (((arow + mi * 16) * ASTRIDE) + acol + ks * 8) * 4;
                ldsm4(ra[mi][0], ra[mi][1], ra[mi][2], ra[mi][3], addr);
            }
#pragma unroll
            for (int mi = 0; mi < 4; mi++)
#pragma unroll
                for (int ni = 0; ni < 4; ni++)
                    mma_tf32(acc[mi][ni], ra[mi][0], ra[mi][1], ra[mi][2], ra[mi][3],
                             rb[ni][0], rb[ni][1]);
        }
        __syncthreads();
    }

#pragma unroll
    for (int mi = 0; mi < 4; mi++) {
        const int row0 = bm + wm + mi * 16 + gr;
        const int row1 = row0 + 8;
#pragma unroll
        for (int ni = 0; ni < 4; ni++) {
            const int col = bn + wn + ni * 8 + 2 * tg;
            float v0 = acc[mi][ni][0], v1 = acc[mi][ni][1];
            float v2 = acc[mi][ni][2], v3 = acc[mi][ni][3];
            if (EPI == 1) {
                const float bb0 = bias[col], bb1 = bias[col + 1];
                v0 = f2tf_f(gelu_exact(v0 + bb0)); v1 = f2tf_f(gelu_exact(v1 + bb1));
                v2 = f2tf_f(gelu_exact(v2 + bb0)); v3 = f2tf_f(gelu_exact(v3 + bb1));
            }
            if (EPI == 2) {
                const float bb0 = bias[col], bb1 = bias[col + 1];
                const float2 r0 = *reinterpret_cast<const float2*>(&res[(size_t)row0 * N + col]);
                const float2 r1 = *reinterpret_cast<const float2*>(&res[(size_t)row1 * N + col]);
                v0 += bb0 + r0.x; v1 += bb1 + r0.y;
                v2 += bb0 + r1.x; v3 += bb1 + r1.y;
            }
            if (EPI == 3) {
                v0 = f2tf_f(v0); v1 = f2tf_f(v1);
                v2 = f2tf_f(v2); v3 = f2tf_f(v3);
            }
            *reinterpret_cast<float2*>(&C[(size_t)row0 * N + col]) = make_float2(v0, v1);
            *reinterpret_cast<float2*>(&C[(size_t)row1 * N + col]) = make_float2(v2, v3);
        }
    }
}

// ---------------- tensor-core causal flash attention (tf32) ----------------
// CTA: 128 q-rows, 8 warps (16 q-rows each, full 64 k-cols). K tiles of 64.
// qkv is pre-rounded to tf32 by gemm<3>.
#define QLD 68
#define KLD 72
#define ATT_SMEM ((128*QLD + 64*KLD + 64*KLD + 128*QLD) * 4)

__global__ void __launch_bounds__(256) attn_kernel(
    const float* __restrict__ qkv, float* __restrict__ O)
{
    const int qt = blockIdx.x;          // 0..15 (128-row q tiles)
    const int bh = blockIdx.y;
    const int bb = bh >> 4, hh = bh & 15;
    const int tid = threadIdx.x;
    const int lane = tid & 31, wid = tid >> 5;
    const int gr = lane >> 2, tg = lane & 3;
    const size_t rowbase = (size_t)bb * TSEQ;
    const int qoff = hh * DH;
    const int koff = DM + hh * DH;
    const int voff = 2 * DM + hh * DH;
    const int q0 = qt * 128;
    const int wr = wid * 16;            // warp's q-row base in tile

    extern __shared__ float sm[];
    float* Qs = sm;                       // [128][QLD]
    float* Kt = Qs + 128 * QLD;           // [d=64][KLD]  (K transposed)
    float* Vs = Kt + 64 * KLD;            // [kr=64][KLD] (V natural)
    float* Ps = Vs + 64 * KLD;            // [128][QLD]
    const uint32_t Qs_u = (uint32_t)__cvta_generic_to_shared(Qs);
    const uint32_t Ps_u = (uint32_t)__cvta_generic_to_shared(Ps);

    const int arow = (lane & 7) + 8 * ((lane >> 3) & 1);
    const int acol = (lane >> 4) * 4;

    // load Q tile (pre-scaled by 1/8; exact power of two, stays tf32)
    for (int e = tid; e < 128 * 64; e += 256) {
        const int r = e >> 6, d = e & 63;
        Qs[r * QLD + d] = qkv[(rowbase + q0 + r) * (size_t)(3 * DM) + qoff + d] * 0.125f;
    }

    float oacc[8][4];
    float sacc[8][4];
#pragma unroll
    for (int i = 0; i < 8; i++)
#pragma unroll
        for (int r = 0; r < 4; r++) oacc[i][r] = 0.f;
    float m0 = -1e30f, m1 = -1e30f, l0 = 0.f, l1 = 0.f;

    const int kt_max = 2 * qt + 1;
    for (int kt = 0; kt <= kt_max; kt++) {
        const int k0 = kt * 64;
        __syncthreads();
        for (int e = tid; e < 64 * 64; e += 256) {
            const int r = e >> 6, d = e & 63;
            const size_t base = (rowbase + k0 + r) * (size_t)(3 * DM);
            Kt[d * KLD + r] = qkv[base + koff + d];
            Vs[r * KLD + d] = qkv[base + voff + d];
        }
        __syncthreads();

        // ---- S = Q K^T ----
#pragma unroll
        for (int i = 0; i < 8; i++)
#pragma unroll
            for (int r = 0; r < 4; r++) sacc[i][r] = 0.f;
#pragma unroll
        for (int ks = 0; ks < 8; ks++) {
            uint32_t a0, a1, a2, a3;
            ldsm4(a0, a1, a2, a3, Qs_u + (((wr + arow) * QLD) + acol + ks * 8) * 4);
#pragma unroll
            for (int ni = 0; ni < 8; ni++) {
                const int n = ni * 8 + gr;
                const uint32_t b0 = __float_as_uint(Kt[(ks * 8 + tg)     * KLD + n]);
                const uint32_t b1 = __float_as_uint(Kt[(ks * 8 + tg + 4) * KLD + n]);
                mma_tf32(sacc[ni], a0, a1, a2, a3, b0, b1);
            }
        }

        // ---- causal mask (only near-diagonal tiles) ----
        const int row_g0 = q0 + wr + gr, row_g1 = row_g0 + 8;
        if (kt >= 2 * qt) {
#pragma unroll
            for (int ni = 0; ni < 8; ni++) {
                const int c0 = k0 + ni * 8 + 2 * tg, c1 = c0 + 1;
                if (c0 > row_g0) sacc[ni][0] = -1e30f;
                if (c1 > row_g0) sacc[ni][1] = -1e30f;
                if (c0 > row_g1) sacc[ni][2] = -1e30f;
                if (c1 > row_g1) sacc[ni][3] = -1e30f;
            }
        }

        // ---- online softmax ----
        float mx0 = -1e30f, mx1 = -1e30f;
#pragma unroll
        for (int ni = 0; ni < 8; ni++) {
            mx0 = fmaxf(mx0, fmaxf(sacc[ni][0], sacc[ni][1]));
            mx1 = fmaxf(mx1, fmaxf(sacc[ni][2], sacc[ni][3]));
        }
        mx0 = fmaxf(mx0, __shfl_xor_sync(0xffffffffu, mx0, 1));
        mx0 = fmaxf(mx0, __shfl_xor_sync(0xffffffffu, mx0, 2));
        mx1 = fmaxf(mx1, __shfl_xor_sync(0xffffffffu, mx1, 1));
        mx1 = fmaxf(mx1, __shfl_xor_sync(0xffffffffu, mx1, 2));
        const float mn0 = fmaxf(m0, mx0), mn1 = fmaxf(m1, mx1);
        const float al0 = __expf(m0 - mn0), al1 = __expf(m1 - mn1);
        float rs0 = 0.f, rs1 = 0.f;
#pragma unroll
        for (int ni = 0; ni < 8; ni++) {
            float p00 = __expf(sacc[ni][0] - mn0);
            float p01 = __expf(sacc[ni][1] - mn0);
            float p10 = __expf(sacc[ni][2] - mn1);
            float p11 = __expf(sacc[ni][3] - mn1);
            rs0 += p00 + p01; rs1 += p10 + p11;
            const int c = ni * 8 + 2 * tg;
            Ps[(wr + gr)     * QLD + c] = f2tf_f(p00);
            Ps[(wr + gr)     * QLD + c + 1] = f2tf_f(p01);
            Ps[(wr + gr + 8) * QLD + c] = f2tf_f(p10);
            Ps[(wr + gr + 8) * QLD + c + 1] = f2tf_f(p11);
        }
        rs0 += __shfl_xor_sync(0xffffffffu, rs0, 1);
        rs0 += __shfl_xor_sync(0xffffffffu, rs0, 2);
        rs1 += __shfl_xor_sync(0xffffffffu, rs1, 1);
        rs1 += __shfl_xor_sync(0xffffffffu, rs1, 2);
        l0 = l0 * al0 + rs0; l1 = l1 * al1 + rs1;
        m0 = mn0; m1 = mn1;
#pragma unroll
        for (int ni = 0; ni < 8; ni++) {
            oacc[ni][0] *= al0; oacc[ni][1] *= al0;
            oacc[ni][2] *= al1; oacc[ni][3] *= al1;
        }
        __syncthreads();

        // ---- O += P V ----
#pragma unroll
        for (int ks = 0; ks < 8; ks++) {
            uint32_t a0, a1, a2, a3;
            ldsm4(a0, a1, a2, a3, Ps_u + (((wr + arow) * QLD) + acol + ks * 8) * 4);
#pragma unroll
            for (int ni = 0; ni < 8; ni++) {
                const int n = ni * 8 + gr;
                const uint32_t b0 = __float_as_uint(Vs[(ks * 8 + tg)     * KLD + n]);
                const uint32_t b1 = __float_as_uint(Vs[(ks * 8 + tg + 4) * KLD + n]);
                mma_tf32(oacc[ni], a0, a1, a2, a3, b0, b1);
            }
        }
    }

    // ---- write O (tf32-rounded; feeds the next GEMM's A) ----
    const float i0 = 1.0f / l0, i1 = 1.0f / l1;
    const size_t r0 = (rowbase + q0 + wr + gr) * (size_t)DM + hh * DH;
    const size_t r1 = r0 + 8 * DM;
#pragma unroll
    for (int ni = 0; ni < 8; ni++) {
        const int c = ni * 8 + 2 * tg;
        *reinterpret_cast<float2*>(&O[r0 + c]) =
            make_float2(f2tf_f(oacc[ni][0] * i0), f2tf_f(oacc[ni][1] * i0));
        *reinterpret_cast<float2*>(&O[r1 + c]) =
            make_float2(f2tf_f(oacc[ni][2] * i1), f2tf_f(oacc[ni][3] * i1));
    }
}

// ---------------- launcher ----------------
extern "C" void kernel_launch(void* const* d_in, const int* in_sizes, int n_in,
                              void* d_out, int out_size)
{
    const float* x     = (const float*)d_in[0];
    const float* ln1_g = (const float*)d_in[1];
    const float* ln1_b = (const float*)d_in[2];
    const float* w_qkv = (const float*)d_in[3];
    const float* w_out = (const float*)d_in[4];
    const float* b_out = (const float*)d_in[5];
    const float* ln2_g = (const float*)d_in[6];
    const float* ln2_b = (const float*)d_in[7];
    const float* w1    = (const float*)d_in[8];
    const float* b1    = (const float*)d_in[9];
    const float* w2    = (const float*)d_in[10];
    const float* b2    = (const float*)d_in[11];
    float* out = (float*)d_out;

    float *h, *qkv, *o, *x2, *ff, *wc;
    cudaGetSymbolAddress((void**)&h,   g_h);
    cudaGetSymbolAddress((void**)&qkv, g_qkv);
    cudaGetSymbolAddress((void**)&o,   g_o);
    cudaGetSymbolAddress((void**)&x2,  g_x2);
    cudaGetSymbolAddress((void**)&ff,  g_ff);
    cudaGetSymbolAddress((void**)&wc,  g_wc);

    float* wqkv_t = wc;
    float* wout_t = wqkv_t + DM * 3 * DM;
    float* w1_t   = wout_t + DM * DM;
    float* w2_t   = w1_t + DM * DFF;

    cudaFuncSetAttribute(attn_kernel,
                         cudaFuncAttributeMaxDynamicSharedMemorySize, ATT_SMEM);
    cudaFuncSetAttribute(gemm_tf32<0>,
                         cudaFuncAttributeMaxDynamicSharedMemorySize, GEMM_SMEM);
    cudaFuncSetAttribute(gemm_tf32<1>,
                         cudaFuncAttributeMaxDynamicSharedMemorySize, GEMM_SMEM);
    cudaFuncSetAttribute(gemm_tf32<2>,
                         cudaFuncAttributeMaxDynamicSharedMemorySize, GEMM_SMEM);
    cudaFuncSetAttribute(gemm_tf32<3>,
                         cudaFuncAttributeMaxDynamicSharedMemorySize, GEMM_SMEM);

    // 0) pre-round weights to tf32
    round_kernel<<<(DM*3*DM)/1024, 256>>>(w_qkv, wqkv_t, DM*3*DM);
    round_kernel<<<(DM*DM)/1024,   256>>>(w_out, wout_t, DM*DM);
    round_kernel<<<(DM*DFF)/1024,  256>>>(w1,    w1_t,   DM*DFF);
    round_kernel<<<(DFF*DM)/1024,  256>>>(w2,    w2_t,   DFF*DM);

    // 1) h = LN1(x)  (tf32-rounded)
    ln_kernel<<<NTOK, 256>>>(x, ln1_g, ln1_b, h);
    // 2) qkv = h @ w_qkv  (tf32-rounded out)
    gemm_tf32<3><<<dim3(3 * DM / 128, NTOK / 128), 256, GEMM_SMEM>>>(
        h, wqkv_t, nullptr, nullptr, qkv, NTOK, 3 * DM, DM);
    // 3) o = causal_attention(qkv)  (tensor-core, tf32-rounded out)
    attn_kernel<<<dim3(TSEQ / 128, 4 * NH), 256, ATT_SMEM>>>(qkv, o);
    // 4) x2 = x + o @ w_out + b_out  (full fp32)
    gemm_tf32<2><<<dim3(DM / 128, NTOK / 128), 256, GEMM_SMEM>>>(
        o, wout_t, b_out, x, x2, NTOK, DM, DM);
    // 5) h = LN2(x2)  (tf32-rounded)
    ln_kernel<<<NTOK, 256>>>(x2, ln2_g, ln2_b, h);
    // 6) ff = gelu(h @ w1 + b1)  (tf32-rounded)
    gemm_tf32<1><<<dim3(DFF / 128, NTOK / 128), 256, GEMM_SMEM>>>(
        h, w1_t, b1, nullptr, ff, NTOK, DFF, DM);
    // 7) out = x2 + ff @ w2 + b2  (full fp32)
    gemm_tf32<2><<<dim3(DM / 128, NTOK / 128), 256, GEMM_SMEM>>>(
        ff, w2_t, b2, x2, out, NTOK, DM, DFF);
}

// round 6
// speedup vs baseline: 3.4028x; 1.0067x over previous
#include <cuda_runtime.h>
#include <math.h>
#include <stdint.h>

#define NTOK   8192      // B*T
#define DM     1024
#define DFF    4096
#define TSEQ   2048
#define NH     16
#define DH     64

// ---------------- scratch (static device globals; no allocation) ----------------
__device__ float g_h  [NTOK * DM];       // LN output (tf32-rounded)
__device__ float g_qkv[NTOK * 3 * DM];   // qkv projections (tf32-rounded)
__device__ float g_o  [NTOK * DM];       // attention output (tf32-rounded)
__device__ float g_x2 [NTOK * DM];       // residual after attention (full fp32)
__device__ float g_ff [NTOK * DFF];      // gelu output (tf32-rounded)
__device__ float g_wc [DM*3*DM + DM*DM + DM*DFF + DFF*DM];  // tf32 weights

__device__ __forceinline__ uint32_t f2tf(float f) {
    uint32_t u;
    asm("cvt.rna.tf32.f32 %0, %1;" : "=r"(u) : "f"(f));
    return u;
}
__device__ __forceinline__ float f2tf_f(float f) {
    return __uint_as_float(f2tf(f));
}

// ---------------- weight pre-round to tf32 ----------------
__global__ void __launch_bounds__(256) round_kernel(
    const float* __restrict__ src, float* __restrict__ dst, int n)
{
    int i = (blockIdx.x * 256 + threadIdx.x) * 4;
    if (i < n) {
        float4 v = *reinterpret_cast<const float4*>(src + i);
        v.x = f2tf_f(v.x); v.y = f2tf_f(v.y);
        v.z = f2tf_f(v.z); v.w = f2tf_f(v.w);
        *reinterpret_cast<float4*>(dst + i) = v;
    }
}

// ---------------- LayerNorm (tf32-rounded output) ----------------
__global__ void __launch_bounds__(256) ln_kernel(
    const float* __restrict__ x, const float* __restrict__ g,
    const float* __restrict__ b, float* __restrict__ out)
{
    const int row = blockIdx.x;
    const float* xr = x + (size_t)row * DM;
    float v[4];
    float s = 0.f, s2 = 0.f;
#pragma unroll
    for (int i = 0; i < 4; i++) {
        v[i] = xr[threadIdx.x + i * 256];
        s += v[i]; s2 += v[i] * v[i];
    }
#pragma unroll
    for (int off = 16; off; off >>= 1) {
        s  += __shfl_xor_sync(0xffffffffu, s,  off);
        s2 += __shfl_xor_sync(0xffffffffu, s2, off);
    }
    __shared__ float ss[8], ss2[8];
    const int w = threadIdx.x >> 5, ln = threadIdx.x & 31;
    if (ln == 0) { ss[w] = s; ss2[w] = s2; }
    __syncthreads();
    s = 0.f; s2 = 0.f;
#pragma unroll
    for (int i = 0; i < 8; i++) { s += ss[i]; s2 += ss2[i]; }
    const float mean = s * (1.0f / DM);
    const float var  = s2 * (1.0f / DM) - mean * mean;
    const float rstd = rsqrtf(var + 1e-5f);
    float* orow = out + (size_t)row * DM;
#pragma unroll
    for (int i = 0; i < 4; i++) {
        const int c = threadIdx.x + i * 256;
        orow[c] = f2tf_f((v[i] - mean) * rstd * g[c] + b[c]);
    }
}

// ---------------- TF32 tensor-core GEMM (inputs pre-rounded) ----------------
// EPI: 0 none, 1 bias+GELU (tf32-rounded out), 2 bias+residual (fp32 out),
//      3 tf32-round only.
__device__ __forceinline__ float gelu_exact(float x) {
    return 0.5f * x * (1.0f + erff(x * 0.70710678118654752f));
}
__device__ __forceinline__ void ldsm4(uint32_t& r0, uint32_t& r1,
                                      uint32_t& r2, uint32_t& r3, uint32_t addr) {
    asm volatile("ldmatrix.sync.aligned.m8n8.x4.shared.b16 {%0,%1,%2,%3}, [%4];\n"
                 : "=r"(r0), "=r"(r1), "=r"(r2), "=r"(r3) : "r"(addr));
}
__device__ __forceinline__ void mma_tf32(float* c,
    uint32_t a0, uint32_t a1, uint32_t a2, uint32_t a3, uint32_t b0, uint32_t b1) {
    asm volatile(
        "mma.sync.aligned.m16n8k8.row.col.f32.tf32.tf32.f32 "
        "{%0,%1,%2,%3}, {%4,%5,%6,%7}, {%8,%9}, {%0,%1,%2,%3};\n"
        : "+f"(c[0]), "+f"(c[1]), "+f"(c[2]), "+f"(c[3])
        : "r"(a0), "r"(a1), "r"(a2), "r"(a3), "r"(b0), "r"(b1));
}
__device__ __forceinline__ void cp16(float* dst, const float* src) {
    uint32_t d = (uint32_t)__cvta_generic_to_shared(dst);
    asm volatile("cp.async.cg.shared.global [%0], [%1], 16;\n" :: "r"(d), "l"(src));
}

#define ASTRIDE 36
#define BSTRIDE 136
#define AS_SZ   (128 * ASTRIDE)
#define BS_SZ   (32 * BSTRIDE)
#define STAGE_F (AS_SZ + BS_SZ)
#define GEMM_SMEM (3 * STAGE_F * 4)

template<int EPI>
__global__ void __launch_bounds__(256, 2) gemm_tf32(
    const float* __restrict__ A, const float* __restrict__ Bm,
    const float* __restrict__ bias, const float* __restrict__ res,
    float* __restrict__ C, int M, int N, int K)
{
    extern __shared__ float sm[];
    const int tid  = threadIdx.x;
    const int lane = tid & 31, wid = tid >> 5;
    const int bm = blockIdx.y * 128, bn = blockIdx.x * 128;
    const int wm = (wid >> 2) * 64;
    const int wn = (wid & 3) * 32;
    const int gr = lane >> 2, tg = lane & 3;

    const uint32_t smem_u32 = (uint32_t)__cvta_generic_to_shared(sm);
    const int arow = wm + (lane & 7) + 8 * ((lane >> 3) & 1);
    const int acol = (lane >> 4) * 4;

    float acc[4][4][4];
#pragma unroll
    for (int i = 0; i < 4; i++)
#pragma unroll
        for (int j = 0; j < 4; j++)
#pragma unroll
            for (int r = 0; r < 4; r++) acc[i][j][r] = 0.f;

    const int KT = K >> 5;

    auto issue = [&](int kt) {
        const int stg = kt % 3;
        const int k0 = kt << 5;
        float* As = sm + stg * STAGE_F;
        float* Bs = As + AS_SZ;
#pragma unroll
        for (int i = 0; i < 4; i++) {
            const int c = tid + i * 256;
            const int row = c >> 3, kc = (c & 7) * 4;
            cp16(As + row * ASTRIDE + kc, A + (size_t)(bm + row) * K + k0 + kc);
        }
#pragma unroll
        for (int i = 0; i < 4; i++) {
            const int c = tid + i * 256;
            const int row = c >> 5, nc = (c & 31) * 4;
            cp16(Bs + row * BSTRIDE + nc, Bm + (size_t)(k0 + row) * N + bn + nc);
        }
    };

    issue(0);
    asm volatile("cp.async.commit_group;\n");
    if (KT > 1) { issue(1); asm volatile("cp.async.commit_group;\n"); }

    for (int kt = 0; kt < KT; kt++) {
        const int cur = kt % 3;
        if (kt + 1 < KT) asm volatile("cp.async.wait_group 1;\n");
        else             asm volatile("cp.async.wait_group 0;\n");
        __syncthreads();
        if (kt + 2 < KT) { issue(kt + 2); asm volatile("cp.async.commit_group;\n"); }

        const uint32_t As_u = smem_u32 + (cur * STAGE_F) * 4;
        const float* Bs = sm + cur * STAGE_F + AS_SZ;

#pragma unroll
        for (int ks = 0; ks < 4; ks++) {
            uint32_t rb[4][2];
#pragma unroll
            for (int ni = 0; ni < 4; ni++) {
                const int nidx = wn + ni * 8 + gr;
                rb[ni][0] = __float_as_uint(Bs[(ks * 8 + tg)     * BSTRIDE + nidx]);
                rb[ni][1] = __float_as_uint(Bs[(ks * 8 + tg + 4) * BSTRIDE + nidx]);
            }
            uint32_t ra[4][4];
#pragma unroll
            for (int mi = 0; mi < 4; mi++) {
                const uint32_t addr = As_u +
                    (((arow + mi * 16) * ASTRIDE) + acol + ks * 8) * 4;
                ldsm4(ra[mi][0], ra[mi][1], ra[mi][2], ra[mi][3], addr);
            }
#pragma unroll
            for (int mi = 0; mi < 4; mi++)
#pragma unroll
                for (int ni = 0; ni < 4; ni++)
                    mma_tf32(acc[mi][ni], ra[mi][0], ra[mi][1], ra[mi][2], ra[mi][3],
                             rb[ni][0], rb[ni][1]);
        }
        __syncthreads();
    }

#pragma unroll
    for (int mi = 0; mi < 4; mi++) {
        const int row0 = bm + wm + mi * 16 + gr;
        const int row1 = row0 + 8;
#pragma unroll
        for (int ni = 0; ni < 4; ni++) {
            const int col = bn + wn + ni * 8 + 2 * tg;
            float v0 = acc[mi][ni][0], v1 = acc[mi][ni][1];
            float v2 = acc[mi][ni][2], v3 = acc[mi][ni][3];
            if (EPI == 1) {
                const float bb0 = bias[col], bb1 = bias[col + 1];
                v0 = f2tf_f(gelu_exact(v0 + bb0)); v1 = f2tf_f(gelu_exact(v1 + bb1));
                v2 = f2tf_f(gelu_exact(v2 + bb0)); v3 = f2tf_f(gelu_exact(v3 + bb1));
            }
            if (EPI == 2) {
                const float bb0 = bias[col], bb1 = bias[col + 1];
                const float2 r0 = *reinterpret_cast<const float2*>(&res[(size_t)row0 * N + col]);
                const float2 r1 = *reinterpret_cast<const float2*>(&res[(size_t)row1 * N + col]);
                v0 += bb0 + r0.x; v1 += bb1 + r0.y;
                v2 += bb0 + r1.x; v3 += bb1 + r1.y;
            }
            if (EPI == 3) {
                v0 = f2tf_f(v0); v1 = f2tf_f(v1);
                v2 = f2tf_f(v2); v3 = f2tf_f(v3);
            }
            *reinterpret_cast<float2*>(&C[(size_t)row0 * N + col]) = make_float2(v0, v1);
            *reinterpret_cast<float2*>(&C[(size_t)row1 * N + col]) = make_float2(v2, v3);
        }
    }
}

// ---------------- tensor-core causal flash attention (tf32) ----------------
#define QLD 68
#define KLD 72
#define ATT_SMEM ((128*QLD + 64*KLD + 64*KLD + 128*QLD) * 4)

__global__ void __launch_bounds__(256, 2) attn_kernel(
    const float* __restrict__ qkv, float* __restrict__ O)
{
    const int qt = blockIdx.x;          // 0..15 (128-row q tiles)
    const int bh = blockIdx.y;
    const int bb = bh >> 4, hh = bh & 15;
    const int tid = threadIdx.x;
    const int lane = tid & 31, wid = tid >> 5;
    const int gr = lane >> 2, tg = lane & 3;
    const size_t rowbase = (size_t)bb * TSEQ;
    const int qoff = hh * DH;
    const int koff = DM + hh * DH;
    const int voff = 2 * DM + hh * DH;
    const int q0 = qt * 128;
    const int wr = wid * 16;            // warp's q-row base in tile

    extern __shared__ float sm[];
    float* Qs = sm;                       // [128][QLD]
    float* Kt = Qs + 128 * QLD;           // [d=64][KLD]  (K transposed)
    float* Vs = Kt + 64 * KLD;            // [kr=64][KLD] (V natural)
    float* Ps = Vs + 64 * KLD;            // [128][QLD]
    const uint32_t Qs_u = (uint32_t)__cvta_generic_to_shared(Qs);
    const uint32_t Ps_u = (uint32_t)__cvta_generic_to_shared(Ps);

    const int arow = (lane & 7) + 8 * ((lane >> 3) & 1);
    const int acol = (lane >> 4) * 4;

    // load Q tile (pre-scaled by 1/8; exact power of two, stays tf32)
    for (int e = tid; e < 128 * 64; e += 256) {
        const int r = e >> 6, d = e & 63;
        Qs[r * QLD + d] = qkv[(rowbase + q0 + r) * (size_t)(3 * DM) + qoff + d] * 0.125f;
    }

    float oacc[8][4];
    float sacc[8][4];
#pragma unroll
    for (int i = 0; i < 8; i++)
#pragma unroll
        for (int r = 0; r < 4; r++) oacc[i][r] = 0.f;
    float m0 = -1e30f, m1 = -1e30f, l0 = 0.f, l1 = 0.f;

    const int kt_max = 2 * qt + 1;
    for (int kt = 0; kt <= kt_max; kt++) {
        const int k0 = kt * 64;
        __syncthreads();
        for (int e = tid; e < 64 * 64; e += 256) {
            const int r = e >> 6, d = e & 63;
            const size_t base = (rowbase + k0 + r) * (size_t)(3 * DM);
            Kt[d * KLD + r] = qkv[base + koff + d];
            Vs[r * KLD + d] = qkv[base + voff + d];
        }
        __syncthreads();

        // ---- S = Q K^T ----
#pragma unroll
        for (int i = 0; i < 8; i++)
#pragma unroll
            for (int r = 0; r < 4; r++) sacc[i][r] = 0.f;
#pragma unroll
        for (int ks = 0; ks < 8; ks++) {
            uint32_t a0, a1, a2, a3;
            ldsm4(a0, a1, a2, a3, Qs_u + (((wr + arow) * QLD) + acol + ks * 8) * 4);
#pragma unroll
            for (int ni = 0; ni < 8; ni++) {
                const int n = ni * 8 + gr;
                const uint32_t b0 = __float_as_uint(Kt[(ks * 8 + tg)     * KLD + n]);
                const uint32_t b1 = __float_as_uint(Kt[(ks * 8 + tg + 4) * KLD + n]);
                mma_tf32(sacc[ni], a0, a1, a2, a3, b0, b1);
            }
        }

        // ---- causal mask (only near-diagonal tiles) ----
        const int row_g0 = q0 + wr + gr, row_g1 = row_g0 + 8;
        if (kt >= 2 * qt) {
#pragma unroll
            for (int ni = 0; ni < 8; ni++) {
                const int c0 = k0 + ni * 8 + 2 * tg, c1 = c0 + 1;
                if (c0 > row_g0) sacc[ni][0] = -1e30f;
                if (c1 > row_g0) sacc[ni][1] = -1e30f;
                if (c0 > row_g1) sacc[ni][2] = -1e30f;
                if (c1 > row_g1) sacc[ni][3] = -1e30f;
            }
        }

        // ---- online softmax ----
        float mx0 = -1e30f, mx1 = -1e30f;
#pragma unroll
        for (int ni = 0; ni < 8; ni++) {
            mx0 = fmaxf(mx0, fmaxf(sacc[ni][0], sacc[ni][1]));
            mx1 = fmaxf(mx1, fmaxf(sacc[ni][2], sacc[ni][3]));
        }
        mx0 = fmaxf(mx0, __shfl_xor_sync(0xffffffffu, mx0, 1));
        mx0 = fmaxf(mx0, __shfl_xor_sync(0xffffffffu, mx0, 2));
        mx1 = fmaxf(mx1, __shfl_xor_sync(0xffffffffu, mx1, 1));
        mx1 = fmaxf(mx1, __shfl_xor_sync(0xffffffffu, mx1, 2));
        const float mn0 = fmaxf(m0, mx0), mn1 = fmaxf(m1, mx1);
        const float al0 = __expf(m0 - mn0), al1 = __expf(m1 - mn1);
        float rs0 = 0.f, rs1 = 0.f;
#pragma unroll
        for (int ni = 0; ni < 8; ni++) {
            float p00 = __expf(sacc[ni][0] - mn0);
            float p01 = __expf(sacc[ni][1] - mn0);
            float p10 = __expf(sacc[ni][2] - mn1);
            float p11 = __expf(sacc[ni][3] - mn1);
            rs0 += p00 + p01; rs1 += p10 + p11;
            const int c = ni * 8 + 2 * tg;
            Ps[(wr + gr)     * QLD + c] = f2tf_f(p00);
            Ps[(wr + gr)     * QLD + c + 1] = f2tf_f(p01);
            Ps[(wr + gr + 8) * QLD + c] = f2tf_f(p10);
            Ps[(wr + gr + 8) * QLD + c + 1] = f2tf_f(p11);
        }
        rs0 += __shfl_xor_sync(0xffffffffu, rs0, 1);
        rs0 += __shfl_xor_sync(0xffffffffu, rs0, 2);
        rs1 += __shfl_xor_sync(0xffffffffu, rs1, 1);
        rs1 += __shfl_xor_sync(0xffffffffu, rs1, 2);
        l0 = l0 * al0 + rs0; l1 = l1 * al1 + rs1;
        m0 = mn0; m1 = mn1;
#pragma unroll
        for (int ni = 0; ni < 8; ni++) {
            oacc[ni][0] *= al0; oacc[ni][1] *= al0;
            oacc[ni][2] *= al1; oacc[ni][3] *= al1;
        }
        __syncthreads();

        // ---- O += P V ----
#pragma unroll
        for (int ks = 0; ks < 8; ks++) {
            uint32_t a0, a1, a2, a3;
            ldsm4(a0, a1, a2, a3, Ps_u + (((wr + arow) * QLD) + acol + ks * 8) * 4);
#pragma unroll
            for (int ni = 0; ni < 8; ni++) {
                const int n = ni * 8 + gr;
                const uint32_t b0 = __float_as_uint(Vs[(ks * 8 + tg)     * KLD + n]);
                const uint32_t b1 = __float_as_uint(Vs[(ks * 8 + tg + 4) * KLD + n]);
                mma_tf32(oacc[ni], a0, a1, a2, a3, b0, b1);
            }
        }
    }

    // ---- write O (tf32-rounded; feeds the next GEMM's A) ----
    const float i0 = 1.0f / l0, i1 = 1.0f / l1;
    const size_t r0 = (rowbase + q0 + wr + gr) * (size_t)DM + hh * DH;
    const size_t r1 = r0 + 8 * DM;
#pragma unroll
    for (int ni = 0; ni < 8; ni++) {
        const int c = ni * 8 + 2 * tg;
        *reinterpret_cast<float2*>(&O[r0 + c]) =
            make_float2(f2tf_f(oacc[ni][0] * i0), f2tf_f(oacc[ni][1] * i0));
        *reinterpret_cast<float2*>(&O[r1 + c]) =
            make_float2(f2tf_f(oacc[ni][2] * i1), f2tf_f(oacc[ni][3] * i1));
    }
}

// ---------------- launcher ----------------
extern "C" void kernel_launch(void* const* d_in, const int* in_sizes, int n_in,
                              void* d_out, int out_size)
{
    const float* x     = (const float*)d_in[0];
    const float* ln1_g = (const float*)d_in[1];
    const float* ln1_b = (const float*)d_in[2];
    const float* w_qkv = (const float*)d_in[3];
    const float* w_out = (const float*)d_in[4];
    const float* b_out = (const float*)d_in[5];
    const float* ln2_g = (const float*)d_in[6];
    const float* ln2_b = (const float*)d_in[7];
    const float* w1    = (const float*)d_in[8];
    const float* b1    = (const float*)d_in[9];
    const float* w2    = (const float*)d_in[10];
    const float* b2    = (const float*)d_in[11];
    float* out = (float*)d_out;

    float *h, *qkv, *o, *x2, *ff, *wc;
    cudaGetSymbolAddress((void**)&h,   g_h);
    cudaGetSymbolAddress((void**)&qkv, g_qkv);
    cudaGetSymbolAddress((void**)&o,   g_o);
    cudaGetSymbolAddress((void**)&x2,  g_x2);
    cudaGetSymbolAddress((void**)&ff,  g_ff);
    cudaGetSymbolAddress((void**)&wc,  g_wc);

    float* wqkv_t = wc;
    float* wout_t = wqkv_t + DM * 3 * DM;
    float* w1_t   = wout_t + DM * DM;
    float* w2_t   = w1_t + DM * DFF;

    cudaFuncSetAttribute(attn_kernel,
                         cudaFuncAttributeMaxDynamicSharedMemorySize, ATT_SMEM);
    cudaFuncSetAttribute(gemm_tf32<0>,
                         cudaFuncAttributeMaxDynamicSharedMemorySize, GEMM_SMEM);
    cudaFuncSetAttribute(gemm_tf32<1>,
                         cudaFuncAttributeMaxDynamicSharedMemorySize, GEMM_SMEM);
    cudaFuncSetAttribute(gemm_tf32<2>,
                         cudaFuncAttributeMaxDynamicSharedMemorySize, GEMM_SMEM);
    cudaFuncSetAttribute(gemm_tf32<3>,
                         cudaFuncAttributeMaxDynamicSharedMemorySize, GEMM_SMEM);

    // 0) pre-round weights to tf32
    round_kernel<<<(DM*3*DM)/1024, 256>>>(w_qkv, wqkv_t, DM*3*DM);
    round_kernel<<<(DM*DM)/1024,   256>>>(w_out, wout_t, DM*DM);
    round_kernel<<<(DM*DFF)/1024,  256>>>(w1,    w1_t,   DM*DFF);
    round_kernel<<<(DFF*DM)/1024,  256>>>(w2,    w2_t,   DFF*DM);

    // 1) h = LN1(x)  (tf32-rounded)
    ln_kernel<<<NTOK, 256>>>(x, ln1_g, ln1_b, h);
    // 2) qkv = h @ w_qkv  (tf32-rounded out)
    gemm_tf32<3><<<dim3(3 * DM / 128, NTOK / 128), 256, GEMM_SMEM>>>(
        h, wqkv_t, nullptr, nullptr, qkv, NTOK, 3 * DM, DM);
    // 3) o = causal_attention(qkv)  (tensor-core, tf32-rounded out)
    attn_kernel<<<dim3(TSEQ / 128, 4 * NH), 256, ATT_SMEM>>>(qkv, o);
    // 4) x2 = x + o @ w_out + b_out  (full fp32)
    gemm_tf32<2><<<dim3(DM / 128, NTOK / 128), 256, GEMM_SMEM>>>(
        o, wout_t, b_out, x, x2, NTOK, DM, DM);
    // 5) h = LN2(x2)  (tf32-rounded)
    ln_kernel<<<NTOK, 256>>>(x2, ln2_g, ln2_b, h);
    // 6) ff = gelu(h @ w1 + b1)  (tf32-rounded)
    gemm_tf32<1><<<dim3(DFF / 128, NTOK / 128), 256, GEMM_SMEM>>>(
        h, w1_t, b1, nullptr, ff, NTOK, DFF, DM);
    // 7) out = x2 + ff @ w2 + b2  (full fp32)
    gemm_tf32<2><<<dim3(DM / 128, NTOK / 128), 256, GEMM_SMEM>>>(
        ff, w2_t, b2, x2, out, NTOK, DM, DFF);
}

// round 7
// speedup vs baseline: 5.9265x; 1.7417x over previous
#include <cuda_runtime.h>
#include <cuda_fp16.h>
#include <math.h>
#include <stdint.h>

#define NTOK   8192      // B*T
#define DM     1024
#define DFF    4096
#define TSEQ   2048
#define NH     16
#define DH     64

// ---------------- scratch (static device globals; no allocation) ----------------
__device__ __half g_h  [NTOK * DM];       // LN output (fp16)
__device__ __half g_qkv[NTOK * 3 * DM];   // qkv projections (fp16)
__device__ __half g_o  [NTOK * DM];       // attention output (fp16)
__device__ float  g_x2 [NTOK * DM];       // residual after attention (fp32)
__device__ __half g_ff [NTOK * DFF];      // gelu output (fp16)
__device__ __half g_wc [DM*3*DM + DM*DM + DM*DFF + DFF*DM]; // fp16 weights, [n][k]

// ---------------- weight transpose + fp16 convert: out[n][k] = h(in[k][n]) ----
__global__ void __launch_bounds__(256) transpose_h_kernel(
    const float* __restrict__ in, __half* __restrict__ out, int K, int N)
{
    __shared__ float tile[32][33];
    const int n0 = blockIdx.x * 32, k0 = blockIdx.y * 32;
    const int tx = threadIdx.x, ty = threadIdx.y;   // block (32, 8)
#pragma unroll
    for (int i = 0; i < 4; i++)
        tile[ty + i * 8][tx] = in[(size_t)(k0 + ty + i * 8) * N + n0 + tx];
    __syncthreads();
#pragma unroll
    for (int i = 0; i < 4; i++)
        out[(size_t)(n0 + ty + i * 8) * K + k0 + tx] =
            __float2half_rn(tile[tx][ty + i * 8]);
}

// ---------------- LayerNorm: fp32 in -> fp16 out ----------------
__global__ void __launch_bounds__(256) ln_kernel(
    const float* __restrict__ x, const float* __restrict__ g,
    const float* __restrict__ b, __half* __restrict__ out)
{
    const int row = blockIdx.x;
    const float* xr = x + (size_t)row * DM;
    float v[4];
    float s = 0.f, s2 = 0.f;
#pragma unroll
    for (int i = 0; i < 4; i++) {
        v[i] = xr[threadIdx.x + i * 256];
        s += v[i]; s2 += v[i] * v[i];
    }
#pragma unroll
    for (int off = 16; off; off >>= 1) {
        s  += __shfl_xor_sync(0xffffffffu, s,  off);
        s2 += __shfl_xor_sync(0xffffffffu, s2, off);
    }
    __shared__ float ss[8], ss2[8];
    const int w = threadIdx.x >> 5, ln = threadIdx.x & 31;
    if (ln == 0) { ss[w] = s; ss2[w] = s2; }
    __syncthreads();
    s = 0.f; s2 = 0.f;
#pragma unroll
    for (int i = 0; i < 8; i++) { s += ss[i]; s2 += ss2[i]; }
    const float mean = s * (1.0f / DM);
    const float var  = s2 * (1.0f / DM) - mean * mean;
    const float rstd = rsqrtf(var + 1e-5f);
    __half* orow = out + (size_t)row * DM;
#pragma unroll
    for (int i = 0; i < 4; i++) {
        const int c = threadIdx.x + i * 256;
        orow[c] = __float2half_rn((v[i] - mean) * rstd * g[c] + b[c]);
    }
}

// ================ fp16 tensor-core GEMM (f32 accumulate) ================
// C[M,N] = A[M,K] @ W[K,N]; Bt = W^T as [n][k] half rows.
// 128x128 tile, BK=32, 256 threads (2x4 warps, 64x32 per warp), 3-stage cp.async.
// EPI: 0 plain half out, 1 bias+GELU half out, 2 bias+residual float out.
__device__ __forceinline__ float gelu_exact(float x) {
    return 0.5f * x * (1.0f + erff(x * 0.70710678118654752f));
}
__device__ __forceinline__ void ldsm4(uint32_t& r0, uint32_t& r1,
                                      uint32_t& r2, uint32_t& r3, uint32_t addr) {
    asm volatile("ldmatrix.sync.aligned.m8n8.x4.shared.b16 {%0,%1,%2,%3}, [%4];\n"
                 : "=r"(r0), "=r"(r1), "=r"(r2), "=r"(r3) : "r"(addr));
}
__device__ __forceinline__ void ldsm4t(uint32_t& r0, uint32_t& r1,
                                       uint32_t& r2, uint32_t& r3, uint32_t addr) {
    asm volatile("ldmatrix.sync.aligned.m8n8.x4.trans.shared.b16 {%0,%1,%2,%3}, [%4];\n"
                 : "=r"(r0), "=r"(r1), "=r"(r2), "=r"(r3) : "r"(addr));
}
__device__ __forceinline__ void mma_f16(float* c,
    uint32_t a0, uint32_t a1, uint32_t a2, uint32_t a3, uint32_t b0, uint32_t b1) {
    asm volatile(
        "mma.sync.aligned.m16n8k16.row.col.f32.f16.f16.f32 "
        "{%0,%1,%2,%3}, {%4,%5,%6,%7}, {%8,%9}, {%0,%1,%2,%3};\n"
        : "+f"(c[0]), "+f"(c[1]), "+f"(c[2]), "+f"(c[3])
        : "r"(a0), "r"(a1), "r"(a2), "r"(a3), "r"(b0), "r"(b1));
}
__device__ __forceinline__ void cp16(__half* dst, const __half* src) {
    uint32_t d = (uint32_t)__cvta_generic_to_shared(dst);
    asm volatile("cp.async.cg.shared.global [%0], [%1], 16;\n" :: "r"(d), "l"(src));
}

#define GPITCH 40                       // halves per smem row (64B data + 16B pad)
#define G_TILE (128 * GPITCH)           // halves per operand tile
#define G_STAGE (2 * G_TILE)            // halves per stage (A + B)
#define GEMM_SMEM (3 * G_STAGE * 2)     // bytes

template<int EPI>
__global__ void __launch_bounds__(256) gemm_f16(
    const __half* __restrict__ A, const __half* __restrict__ Bt,
    const float* __restrict__ bias, const float* __restrict__ res,
    float* __restrict__ Cf, __half* __restrict__ Ch, int M, int N, int K)
{
    extern __shared__ __half smh[];
    const int tid  = threadIdx.x;
    const int lane = tid & 31, wid = tid >> 5;
    const int bm = blockIdx.y * 128, bn = blockIdx.x * 128;
    const int wm = (wid >> 2) * 64;
    const int wn = (wid & 3) * 32;
    const int gr = lane >> 2, tg = lane & 3;

    const uint32_t smem_u32 = (uint32_t)__cvta_generic_to_shared(smh);
    const int mat  = lane >> 3;         // ldmatrix matrix id 0..3
    const int mrow = lane & 7;

    float acc[4][4][4];
#pragma unroll
    for (int i = 0; i < 4; i++)
#pragma unroll
        for (int j = 0; j < 4; j++)
#pragma unroll
            for (int r = 0; r < 4; r++) acc[i][j][r] = 0.f;

    const int KT = K >> 5;

    auto issue = [&](int kt) {
        const int stg = kt % 3;
        const int k0 = kt << 5;
        __half* As = smh + stg * G_STAGE;
        __half* Bs = As + G_TILE;
#pragma unroll
        for (int i = 0; i < 2; i++) {
            const int c = tid + i * 256;             // 0..511
            const int row = c >> 2, kc = (c & 3) * 8;
            cp16(As + row * GPITCH + kc, A  + (size_t)(bm + row) * K + k0 + kc);
        }
#pragma unroll
        for (int i = 0; i < 2; i++) {
            const int c = tid + i * 256;
            const int row = c >> 2, kc = (c & 3) * 8;
            cp16(Bs + row * GPITCH + kc, Bt + (size_t)(bn + row) * K + k0 + kc);
        }
    };

    issue(0);
    asm volatile("cp.async.commit_group;\n");
    if (KT > 1) { issue(1); asm volatile("cp.async.commit_group;\n"); }

    for (int kt = 0; kt < KT; kt++) {
        const int cur = kt % 3;
        if (kt + 1 < KT) asm volatile("cp.async.wait_group 1;\n");
        else             asm volatile("cp.async.wait_group 0;\n");
        __syncthreads();
        if (kt + 2 < KT) { issue(kt + 2); asm volatile("cp.async.commit_group;\n"); }

        const uint32_t As_u = smem_u32 + (cur * G_STAGE) * 2;
        const uint32_t Bs_u = As_u + G_TILE * 2;

#pragma unroll
        for (int ks = 0; ks < 2; ks++) {
            // B fragments: 2 ldmatrix.x4 cover 4 n8-tiles
            uint32_t rb[4][2];
#pragma unroll
            for (int a = 0; a < 2; a++) {
                const int n_ = wn + a * 16 + (mat >> 1) * 8 + mrow;
                const int k_ = ks * 16 + (mat & 1) * 8;
                uint32_t r0, r1, r2, r3;
                ldsm4(r0, r1, r2, r3, Bs_u + (uint32_t)(n_ * GPITCH + k_) * 2);
                rb[2 * a][0] = r0; rb[2 * a][1] = r1;
                rb[2 * a + 1][0] = r2; rb[2 * a + 1][1] = r3;
            }
            // A fragments: 4 ldmatrix.x4 (one per 16-row m tile)
            uint32_t ra[4][4];
#pragma unroll
            for (int mi = 0; mi < 4; mi++) {
                const int m_ = wm + mi * 16 + ((mat & 1) ? 8 : 0) + mrow;
                const int k_ = ks * 16 + ((mat >> 1) ? 8 : 0);
                ldsm4(ra[mi][0], ra[mi][1], ra[mi][2], ra[mi][3],
                      As_u + (uint32_t)(m_ * GPITCH + k_) * 2);
            }
#pragma unroll
            for (int mi = 0; mi < 4; mi++)
#pragma unroll
                for (int ni = 0; ni < 4; ni++)
                    mma_f16(acc[mi][ni], ra[mi][0], ra[mi][1], ra[mi][2], ra[mi][3],
                            rb[ni][0], rb[ni][1]);
        }
        __syncthreads();
    }

    // ---- epilogue ----
#pragma unroll
    for (int mi = 0; mi < 4; mi++) {
        const int row0 = bm + wm + mi * 16 + gr;
        const int row1 = row0 + 8;
#pragma unroll
        for (int ni = 0; ni < 4; ni++) {
            const int col = bn + wn + ni * 8 + 2 * tg;
            float v0 = acc[mi][ni][0], v1 = acc[mi][ni][1];
            float v2 = acc[mi][ni][2], v3 = acc[mi][ni][3];
            if (EPI == 1) {
                const float bb0 = bias[col], bb1 = bias[col + 1];
                v0 = gelu_exact(v0 + bb0); v1 = gelu_exact(v1 + bb1);
                v2 = gelu_exact(v2 + bb0); v3 = gelu_exact(v3 + bb1);
            }
            if (EPI == 2) {
                const float bb0 = bias[col], bb1 = bias[col + 1];
                const float2 r0 = *reinterpret_cast<const float2*>(&res[(size_t)row0 * N + col]);
                const float2 r1 = *reinterpret_cast<const float2*>(&res[(size_t)row1 * N + col]);
                v0 += bb0 + r0.x; v1 += bb1 + r0.y;
                v2 += bb0 + r1.x; v3 += bb1 + r1.y;
                *reinterpret_cast<float2*>(&Cf[(size_t)row0 * N + col]) = make_float2(v0, v1);
                *reinterpret_cast<float2*>(&Cf[(size_t)row1 * N + col]) = make_float2(v2, v3);
            } else {
                *reinterpret_cast<__half2*>(&Ch[(size_t)row0 * N + col]) =
                    __floats2half2_rn(v0, v1);
                *reinterpret_cast<__half2*>(&Ch[(size_t)row1 * N + col]) =
                    __floats2half2_rn(v2, v3);
            }
        }
    }
}

// ============ fp16 tensor-core causal flash attention ============
// CTA: 128 q-rows, 8 warps (16 q-rows each, all 64 k-cols). K tiles of 64.
#define QPITCH 72
#define KPITCH 72
#define ATT_SMEM ((128*QPITCH + 64*KPITCH + 64*KPITCH + 128*QPITCH) * 2)

__global__ void __launch_bounds__(256) attn_kernel(
    const __half* __restrict__ qkv, __half* __restrict__ O)
{
    const int qt = blockIdx.x;
    const int bh = blockIdx.y;
    const int bb = bh >> 4, hh = bh & 15;
    const int tid = threadIdx.x;
    const int lane = tid & 31, wid = tid >> 5;
    const int gr = lane >> 2, tg = lane & 3;
    const int mat = lane >> 3, mrow = lane & 7;
    const size_t rowbase = (size_t)bb * TSEQ;
    const int qoff = hh * DH;
    const int koff = DM + hh * DH;
    const int voff = 2 * DM + hh * DH;
    const int q0 = qt * 128;
    const int wr = wid * 16;

    extern __shared__ __half smh[];
    __half* Qs = smh;                       // [128][QPITCH]
    __half* Ks = Qs + 128 * QPITCH;         // [kcol 64][KPITCH] (natural)
    __half* Vs = Ks + 64 * KPITCH;          // [kk 64][KPITCH]   (natural)
    __half* Ps = Vs + 64 * KPITCH;          // [128][QPITCH]
    const uint32_t Qs_u = (uint32_t)__cvta_generic_to_shared(Qs);
    const uint32_t Ks_u = (uint32_t)__cvta_generic_to_shared(Ks);
    const uint32_t Vs_u = (uint32_t)__cvta_generic_to_shared(Vs);
    const uint32_t Ps_u = (uint32_t)__cvta_generic_to_shared(Ps);

    // load Q tile (scale by 1/8, exact)
    {
        const __half2 sc = __floats2half2_rn(0.125f, 0.125f);
        for (int e = tid; e < 128 * 32; e += 256) {
            const int r = e >> 5, d2 = e & 31;
            __half2 v = *reinterpret_cast<const __half2*>(
                &qkv[(rowbase + q0 + r) * (size_t)(3 * DM) + qoff + 2 * d2]);
            *reinterpret_cast<__half2*>(&Qs[r * QPITCH + 2 * d2]) = __hmul2(v, sc);
        }
    }

    float oacc[8][4];
    float sacc[8][4];
#pragma unroll
    for (int i = 0; i < 8; i++)
#pragma unroll
        for (int r = 0; r < 4; r++) oacc[i][r] = 0.f;
    float m0 = -1e30f, m1 = -1e30f, l0 = 0.f, l1 = 0.f;

    const int kt_max = 2 * qt + 1;
    for (int kt = 0; kt <= kt_max; kt++) {
        const int k0 = kt * 64;
        __syncthreads();
        for (int e = tid; e < 64 * 32; e += 256) {
            const int r = e >> 5, d2 = e & 31;
            const size_t base = (rowbase + k0 + r) * (size_t)(3 * DM);
            *reinterpret_cast<__half2*>(&Ks[r * KPITCH + 2 * d2]) =
                *reinterpret_cast<const __half2*>(&qkv[base + koff + 2 * d2]);
            *reinterpret_cast<__half2*>(&Vs[r * KPITCH + 2 * d2]) =
                *reinterpret_cast<const __half2*>(&qkv[base + voff + 2 * d2]);
        }
        __syncthreads();

        // ---- S = Q K^T : n = kcol (K natural rows), inner = d ----
#pragma unroll
        for (int i = 0; i < 8; i++)
#pragma unroll
            for (int r = 0; r < 4; r++) sacc[i][r] = 0.f;
#pragma unroll
        for (int ks = 0; ks < 4; ks++) {
            uint32_t a0, a1, a2, a3;
            {
                const int m_ = wr + ((mat & 1) ? 8 : 0) + mrow;
                const int k_ = ks * 16 + ((mat >> 1) ? 8 : 0);
                ldsm4(a0, a1, a2, a3, Qs_u + (uint32_t)(m_ * QPITCH + k_) * 2);
            }
#pragma unroll
            for (int a = 0; a < 4; a++) {
                const int n_ = a * 16 + (mat >> 1) * 8 + mrow;   // kcol
                const int d_ = ks * 16 + (mat & 1) * 8;
                uint32_t b0, b1, b2, b3;
                ldsm4(b0, b1, b2, b3, Ks_u + (uint32_t)(n_ * KPITCH + d_) * 2);
                mma_f16(sacc[2 * a],     a0, a1, a2, a3, b0, b1);
                mma_f16(sacc[2 * a + 1], a0, a1, a2, a3, b2, b3);
            }
        }

        // ---- causal mask ----
        const int row_g0 = q0 + wr + gr, row_g1 = row_g0 + 8;
        if (kt >= 2 * qt) {
#pragma unroll
            for (int ni = 0; ni < 8; ni++) {
                const int c0 = k0 + ni * 8 + 2 * tg, c1 = c0 + 1;
                if (c0 > row_g0) sacc[ni][0] = -1e30f;
                if (c1 > row_g0) sacc[ni][1] = -1e30f;
                if (c0 > row_g1) sacc[ni][2] = -1e30f;
                if (c1 > row_g1) sacc[ni][3] = -1e30f;
            }
        }

        // ---- online softmax ----
        float mx0 = -1e30f, mx1 = -1e30f;
#pragma unroll
        for (int ni = 0; ni < 8; ni++) {
            mx0 = fmaxf(mx0, fmaxf(sacc[ni][0], sacc[ni][1]));
            mx1 = fmaxf(mx1, fmaxf(sacc[ni][2], sacc[ni][3]));
        }
        mx0 = fmaxf(mx0, __shfl_xor_sync(0xffffffffu, mx0, 1));
        mx0 = fmaxf(mx0, __shfl_xor_sync(0xffffffffu, mx0, 2));
        mx1 = fmaxf(mx1, __shfl_xor_sync(0xffffffffu, mx1, 1));
        mx1 = fmaxf(mx1, __shfl_xor_sync(0xffffffffu, mx1, 2));
        const float mn0 = fmaxf(m0, mx0), mn1 = fmaxf(m1, mx1);
        const float al0 = __expf(m0 - mn0), al1 = __expf(m1 - mn1);
        float rs0 = 0.f, rs1 = 0.f;
#pragma unroll
        for (int ni = 0; ni < 8; ni++) {
            float p00 = __expf(sacc[ni][0] - mn0);
            float p01 = __expf(sacc[ni][1] - mn0);
            float p10 = __expf(sacc[ni][2] - mn1);
            float p11 = __expf(sacc[ni][3] - mn1);
            rs0 += p00 + p01; rs1 += p10 + p11;
            const int c = ni * 8 + 2 * tg;
            *reinterpret_cast<__half2*>(&Ps[(wr + gr)     * QPITCH + c]) =
                __floats2half2_rn(p00, p01);
            *reinterpret_cast<__half2*>(&Ps[(wr + gr + 8) * QPITCH + c]) =
                __floats2half2_rn(p10, p11);
        }
        rs0 += __shfl_xor_sync(0xffffffffu, rs0, 1);
        rs0 += __shfl_xor_sync(0xffffffffu, rs0, 2);
        rs1 += __shfl_xor_sync(0xffffffffu, rs1, 1);
        rs1 += __shfl_xor_sync(0xffffffffu, rs1, 2);
        l0 = l0 * al0 + rs0; l1 = l1 * al1 + rs1;
        m0 = mn0; m1 = mn1;
#pragma unroll
        for (int ni = 0; ni < 8; ni++) {
            oacc[ni][0] *= al0; oacc[ni][1] *= al0;
            oacc[ni][2] *= al1; oacc[ni][3] *= al1;
        }
        __syncthreads();

        // ---- O += P V : n = d, inner = kk (V natural -> trans ldmatrix) ----
#pragma unroll
        for (int ks = 0; ks < 4; ks++) {
            uint32_t a0, a1, a2, a3;
            {
                const int m_ = wr + ((mat & 1) ? 8 : 0) + mrow;
                const int k_ = ks * 16 + ((mat >> 1) ? 8 : 0);
                ldsm4(a0, a1, a2, a3, Ps_u + (uint32_t)(m_ * QPITCH + k_) * 2);
            }
#pragma unroll
            for (int a = 0; a < 4; a++) {
                const int kk_ = ks * 16 + (mat & 1) * 8 + mrow;
                const int d_  = a * 16 + (mat >> 1) * 8;
                uint32_t b0, b1, b2, b3;
                ldsm4t(b0, b1, b2, b3, Vs_u + (uint32_t)(kk_ * KPITCH + d_) * 2);
                mma_f16(oacc[2 * a],     a0, a1, a2, a3, b0, b1);
                mma_f16(oacc[2 * a + 1], a0, a1, a2, a3, b2, b3);
            }
        }
    }

    // ---- write O (fp16) ----
    const float i0 = 1.0f / l0, i1 = 1.0f / l1;
    const size_t r0 = (rowbase + q0 + wr + gr) * (size_t)DM + hh * DH;
    const size_t r1 = r0 + 8 * DM;
#pragma unroll
    for (int ni = 0; ni < 8; ni++) {
        const int c = ni * 8 + 2 * tg;
        *reinterpret_cast<__half2*>(&O[r0 + c]) =
            __floats2half2_rn(oacc[ni][0] * i0, oacc[ni][1] * i0);
        *reinterpret_cast<__half2*>(&O[r1 + c]) =
            __floats2half2_rn(oacc[ni][2] * i1, oacc[ni][3] * i1);
    }
}

// ---------------- launcher ----------------
extern "C" void kernel_launch(void* const* d_in, const int* in_sizes, int n_in,
                              void* d_out, int out_size)
{
    const float* x     = (const float*)d_in[0];
    const float* ln1_g = (const float*)d_in[1];
    const float* ln1_b = (const float*)d_in[2];
    const float* w_qkv = (const float*)d_in[3];
    const float* w_out = (const float*)d_in[4];
    const float* b_out = (const float*)d_in[5];
    const float* ln2_g = (const float*)d_in[6];
    const float* ln2_b = (const float*)d_in[7];
    const float* w1    = (const float*)d_in[8];
    const float* b1    = (const float*)d_in[9];
    const float* w2    = (const float*)d_in[10];
    const float* b2    = (const float*)d_in[11];
    float* out = (float*)d_out;

    __half *h, *qkv, *o, *ff, *wc;
    float *x2;
    cudaGetSymbolAddress((void**)&h,   g_h);
    cudaGetSymbolAddress((void**)&qkv, g_qkv);
    cudaGetSymbolAddress((void**)&o,   g_o);
    cudaGetSymbolAddress((void**)&x2,  g_x2);
    cudaGetSymbolAddress((void**)&ff,  g_ff);
    cudaGetSymbolAddress((void**)&wc,  g_wc);

    __half* wqkv_t = wc;                       // [3072][1024]
    __half* wout_t = wqkv_t + DM * 3 * DM;     // [1024][1024]
    __half* w1_t   = wout_t + DM * DM;         // [4096][1024]
    __half* w2_t   = w1_t + DM * DFF;          // [1024][4096]

    cudaFuncSetAttribute(attn_kernel,
                         cudaFuncAttributeMaxDynamicSharedMemorySize, ATT_SMEM);
    cudaFuncSetAttribute(gemm_f16<0>,
                         cudaFuncAttributeMaxDynamicSharedMemorySize, GEMM_SMEM);
    cudaFuncSetAttribute(gemm_f16<1>,
                         cudaFuncAttributeMaxDynamicSharedMemorySize, GEMM_SMEM);
    cudaFuncSetAttribute(gemm_f16<2>,
                         cudaFuncAttributeMaxDynamicSharedMemorySize, GEMM_SMEM);

    // 0) weights: transpose + convert to fp16 ([n][k])
    transpose_h_kernel<<<dim3(3*DM/32, DM/32), dim3(32,8)>>>(w_qkv, wqkv_t, DM, 3*DM);
    transpose_h_kernel<<<dim3(DM/32,   DM/32), dim3(32,8)>>>(w_out, wout_t, DM, DM);
    transpose_h_kernel<<<dim3(DFF/32,  DM/32), dim3(32,8)>>>(w1,    w1_t,   DM, DFF);
    transpose_h_kernel<<<dim3(DM/32,  DFF/32), dim3(32,8)>>>(w2,    w2_t,   DFF, DM);

    // 1) h = LN1(x)
    ln_kernel<<<NTOK, 256>>>(x, ln1_g, ln1_b, h);
    // 2) qkv = h @ w_qkv
    gemm_f16<0><<<dim3(3 * DM / 128, NTOK / 128), 256, GEMM_SMEM>>>(
        h, wqkv_t, nullptr, nullptr, nullptr, qkv, NTOK, 3 * DM, DM);
    // 3) o = causal_attention(qkv)
    attn_kernel<<<dim3(TSEQ / 128, 4 * NH), 256, ATT_SMEM>>>(qkv, o);
    // 4) x2 = x + o @ w_out + b_out  (fp32 out)
    gemm_f16<2><<<dim3(DM / 128, NTOK / 128), 256, GEMM_SMEM>>>(
        o, wout_t, b_out, x, x2, nullptr, NTOK, DM, DM);
    // 5) h = LN2(x2)
    ln_kernel<<<NTOK, 256>>>(x2, ln2_g, ln2_b, h);
    // 6) ff = gelu(h @ w1 + b1)
    gemm_f16<1><<<dim3(DFF / 128, NTOK / 128), 256, GEMM_SMEM>>>(
        h, w1_t, b1, nullptr, nullptr, ff, NTOK, DFF, DM);
    // 7) out = x2 + ff @ w2 + b2  (fp32 out)
    gemm_f16<2><<<dim3(DM / 128, NTOK / 128), 256, GEMM_SMEM>>>(
        ff, w2_t, b2, x2, out, nullptr, NTOK, DM, DFF);
}